// round 14
// baseline (speedup 1.0000x reference)
#include <cuda_runtime.h>
#include <cuda_fp16.h>
#include <cstdint>

#define HID   1024
#define BNUM  8
#define SLEN  2048
#define QLEN  2048

// ---------------- scratch: fp16 operand planes (allocation-free) -----------
__device__ __half g_Qh[(size_t)BNUM * QLEN * HID];
__device__ __half g_Kh[(size_t)BNUM * SLEN * HID];
__device__ __half g_Vh[(size_t)BNUM * SLEN * HID];
__device__ __half g_Wqh[(size_t)HID * HID];
__device__ __half g_Wql[(size_t)HID * HID];
__device__ __half g_Wkh[(size_t)HID * HID];
__device__ __half g_Wkl[(size_t)HID * HID];
__device__ __half g_Wvh[(size_t)HID * HID];
__device__ __half g_Mth[(size_t)HID * HID];          // 32 * Wq^T Wk (hi)
__device__ float  g_MtP[(size_t)4 * HID * HID];      // Mt k-split partials
__device__ __half g_KMh[(size_t)BNUM * SLEN * HID];  // keys*M (hi)
__device__ __half g_Vph[(size_t)BNUM * SLEN * HID];  // V proj (hi)
__device__ __half g_Ph [(size_t)BNUM * SLEN * QLEN]; // exp(scores) f16 (unnorm)
__device__ float  g_part[(size_t)BNUM * 16 * QLEN];  // col-sum partials
__device__ float  g_inv [(size_t)BNUM * QLEN];       // 1 / col sums
__device__ float  g_vrow[(size_t)BNUM * SLEN];       // keys * (Wk^T bq)
__device__ float  g_vec[HID];
__device__ int    g_flag;

// ---------------- geometry ----------------
#define TM   128
#define TN   128
#define TKF  32
#define SLOT 10240         // one plane-tile slot (max of NT 10240 / TN 8704)
#define PNT  80            // NT tile row pitch (64B data + 16B pad)
#define PTR  272           // TRANS tile row pitch (256B data + 16B pad)

// ---------------- PTX helpers ----------------
__device__ __forceinline__ uint32_t smem_u32(const void* p) {
    uint32_t a;
    asm("{ .reg .u64 t; cvta.to.shared.u64 t, %1; cvt.u32.u64 %0, t; }"
        : "=r"(a) : "l"(p));
    return a;
}
__device__ __forceinline__ void cp16(uint32_t s, const void* g) {
    asm volatile("cp.async.cg.shared.global [%0], [%1], 16;"
                 :: "r"(s), "l"(g));
}
__device__ __forceinline__ void cp_commit() {
    asm volatile("cp.async.commit_group;" ::: "memory");
}
template <int N_>
__device__ __forceinline__ void cp_wait() {
    asm volatile("cp.async.wait_group %0;" :: "n"(N_) : "memory");
}
__device__ __forceinline__ void ldsm4(uint32_t* r, uint32_t addr) {
    asm volatile("ldmatrix.sync.aligned.m8n8.x4.shared.b16 {%0,%1,%2,%3}, [%4];"
                 : "=r"(r[0]), "=r"(r[1]), "=r"(r[2]), "=r"(r[3]) : "r"(addr));
}
__device__ __forceinline__ void ldsm4t(uint32_t* r, uint32_t addr) {
    asm volatile("ldmatrix.sync.aligned.m8n8.x4.trans.shared.b16 {%0,%1,%2,%3}, [%4];"
                 : "=r"(r[0]), "=r"(r[1]), "=r"(r[2]), "=r"(r[3]) : "r"(addr));
}
__device__ __forceinline__ void mma16816(float* c, const uint32_t* a,
                                         const uint32_t* b) {
    asm volatile(
        "mma.sync.aligned.m16n8k16.row.col.f32.f16.f16.f32 "
        "{%0,%1,%2,%3}, {%4,%5,%6,%7}, {%8,%9}, {%0,%1,%2,%3};"
        : "+f"(c[0]), "+f"(c[1]), "+f"(c[2]), "+f"(c[3])
        : "r"(a[0]), "r"(a[1]), "r"(a[2]), "r"(a[3]), "r"(b[0]), "r"(b[1]));
}

// ---------------------------------------------------------------------------
// Unified fp16 tensor-core GEMM over pre-converted half planes.
// NT (TRANS=0): C[m,n] = alpha*sum_k A[m,k]*B[n,k], A:[M,K], B:[N,K]
// TN (TRANS=1): C[m,n] = alpha*sum_k A[k,m]*B[k,n], A:[K,M], B:[K,N]
// ASPL/BSPL: lo-residual planes (extra MMA each).
// EPI: 0 = f32 out (+bias) [optionally * rowsc[row]];
//      1 = half out (+bias);
//      2 = exp epilogue: writes f16 exp to Ch, col-sum partials to g_part.
// STAGES: cp.async pipeline depth. GROUP: k-tiles per stage (fewer barriers).
// ---------------------------------------------------------------------------
template <bool TRANS, bool ASPL, bool BSPL, int EPI, int STAGES, int GROUP>
__device__ __forceinline__ void gbody(
    const __half* __restrict__ Ah, const __half* __restrict__ Al,
    const __half* __restrict__ Bh, const __half* __restrict__ Bl,
    float* __restrict__ Cf, __half* __restrict__ Ch,
    const float* __restrict__ bias, const float* __restrict__ rowsc,
    int M, int N, int K, int ldA, int ldB, float alpha,
    size_t sA, size_t sB, size_t sC, int zz_in)
{
    constexpr int NPA   = ASPL ? 2 : 1;
    constexpr int NP    = NPA + (BSPL ? 2 : 1);
    constexpr int SUBSZ = NP * SLOT;        // one k-tile (all planes)
    constexpr int STG   = GROUP * SUBSZ;    // one pipeline stage

    extern __shared__ char sm[];
    const uint32_t sb = smem_u32(sm);

    const int tid  = threadIdx.x;
    const int lane = tid & 31;
    const int w    = tid >> 5;
    const int wm   = w & 1;
    const int wn   = w >> 1;
    const int g    = lane >> 2;
    const int t    = lane & 3;

    const size_t zz = zz_in;
    const __half* Ahb = Ah + zz * sA;
    const __half* Alb = ASPL ? Al + zz * sA : nullptr;
    const __half* Bhb = Bh + zz * sB;
    const __half* Blb = BSPL ? Bl + zz * sB : nullptr;
    const int bm = blockIdx.y * TM;
    const int bn = blockIdx.x * TN;

    // fragment address components
    const int a_r   = ((lane >> 3) & 1) * 8 + (lane & 7);
    const int a_c8  = (lane >> 4) * 8;
    const int b_r   = (lane >> 4) * 8 + (lane & 7);
    const int b_c8  = ((lane >> 3) & 1) * 8;
    const int at_r  = (lane >> 4) * 8 + (lane & 7);
    const int at_c8 = ((lane >> 3) & 1) * 8;
    const int bt_r  = ((lane >> 3) & 1) * 8 + (lane & 7);
    const int bt_c8 = (lane >> 4) * 8;

    float acc[4][4][4];
#pragma unroll
    for (int i = 0; i < 4; i++)
#pragma unroll
        for (int j = 0; j < 4; j++)
#pragma unroll
            for (int e = 0; e < 4; e++) acc[i][j][e] = 0.0f;

    const int NS = K / (TKF * GROUP);   // pipeline stages over K

    // load k-tile kt into sub-slot base st (all planes)
    auto issue_tile = [&](int kt, uint32_t st) {
        if (!TRANS) {
#pragma unroll
            for (int j = 0; j < 2; j++) {
                const int idx = tid * 2 + j;
                const int r = idx >> 2, c = idx & 3;
                const uint32_t so = (uint32_t)(r * PNT + c * 16);
                const size_t goA = (size_t)(bm + r) * ldA + kt * TKF + c * 8;
                const size_t goB = (size_t)(bn + r) * ldB + kt * TKF + c * 8;
                cp16(st + so, Ahb + goA);
                if (ASPL) cp16(st + SLOT + so, Alb + goA);
                cp16(st + NPA * SLOT + so, Bhb + goB);
                if (BSPL) cp16(st + (NPA + 1) * SLOT + so, Blb + goB);
            }
        } else {
#pragma unroll
            for (int j = 0; j < 2; j++) {
                const int idx = tid * 2 + j;
                const int r = idx >> 4, c = idx & 15;
                const uint32_t so = (uint32_t)(r * PTR + c * 16);
                const size_t goA = (size_t)(kt * TKF + r) * ldA + bm + c * 8;
                const size_t goB = (size_t)(kt * TKF + r) * ldB + bn + c * 8;
                cp16(st + so, Ahb + goA);
                if (ASPL) cp16(st + SLOT + so, Alb + goA);
                cp16(st + NPA * SLOT + so, Bhb + goB);
                if (BSPL) cp16(st + (NPA + 1) * SLOT + so, Blb + goB);
            }
        }
    };

    auto issue_stage = [&](int si, int p) {
#pragma unroll
        for (int sg = 0; sg < GROUP; sg++)
            issue_tile(si * GROUP + sg, sb + p * STG + sg * SUBSZ);
    };

    // prologue: fill STAGES-1 stages, one commit group per stage
#pragma unroll
    for (int s = 0; s < STAGES - 1; s++) {
        if (s < NS) issue_stage(s, s);
        cp_commit();
    }

    for (int si = 0; si < NS; si++) {
        const int p = si % STAGES;

        cp_wait<STAGES - 2>();   // stage si resident
        __syncthreads();         // also guards reuse of the stage being refilled

        if (si + STAGES - 1 < NS) issue_stage(si + STAGES - 1,
                                              (si + STAGES - 1) % STAGES);
        cp_commit();             // keep group numbering aligned (may be empty)

#pragma unroll
        for (int sg = 0; sg < GROUP; sg++) {
            const uint32_t sa_hi = sb + p * STG + sg * SUBSZ;
            const uint32_t sa_lo = sa_hi + SLOT;
            const uint32_t sb_hi = sa_hi + NPA * SLOT;
            const uint32_t sb_lo = sb_hi + SLOT;

#pragma unroll
            for (int ks = 0; ks < 2; ks++) {
                const int k0 = ks * 16;

                uint32_t bh[8], bl[8];
#pragma unroll
                for (int j = 0; j < 2; j++) {
                    uint32_t addr;
                    if (!TRANS) {
                        addr = (uint32_t)((wn * 32 + j * 16 + b_r) * PNT +
                                          (k0 + b_c8) * 2);
                        ldsm4(bh + 4 * j, sb_hi + addr);
                        if (BSPL) ldsm4(bl + 4 * j, sb_lo + addr);
                    } else {
                        addr = (uint32_t)((k0 + bt_r) * PTR +
                                          (wn * 32 + j * 16 + bt_c8) * 2);
                        ldsm4t(bh + 4 * j, sb_hi + addr);
                        if (BSPL) ldsm4t(bl + 4 * j, sb_lo + addr);
                    }
                }

                uint32_t ah[4][4], al[4][4];
#pragma unroll
                for (int mf = 0; mf < 4; mf++) {
                    uint32_t addr;
                    if (!TRANS) {
                        addr = (uint32_t)((wm * 64 + mf * 16 + a_r) * PNT +
                                          (k0 + a_c8) * 2);
                        ldsm4(ah[mf], sa_hi + addr);
                        if (ASPL) ldsm4(al[mf], sa_lo + addr);
                    } else {
                        addr = (uint32_t)((k0 + at_r) * PTR +
                                          (wm * 64 + mf * 16 + at_c8) * 2);
                        ldsm4t(ah[mf], sa_hi + addr);
                        if (ASPL) ldsm4t(al[mf], sa_lo + addr);
                    }
                }

#pragma unroll
                for (int mf = 0; mf < 4; mf++)
#pragma unroll
                    for (int nf = 0; nf < 4; nf++) {
                        mma16816(acc[mf][nf], ah[mf], bh + 2 * nf);
                        if (ASPL) mma16816(acc[mf][nf], al[mf], bh + 2 * nf);
                        if (BSPL) mma16816(acc[mf][nf], ah[mf], bl + 2 * nf);
                    }
            }
        }
        // no trailing sync: next iteration's sync (after cp_wait) guards reuse
    }

    // ---------------- epilogues ----------------
    if (EPI == 2) {
        __syncthreads();  // smem 'red' reuses pipeline buffers
        __half* Cb = Ch + zz * sC;
        const float* vr = g_vrow + zz * SLEN;
        float cs[8];
#pragma unroll
        for (int j = 0; j < 8; j++) cs[j] = 0.0f;

#pragma unroll
        for (int mf = 0; mf < 4; mf++) {
            const int row0 = bm + wm * 64 + mf * 16 + g;
            const int row1 = row0 + 8;
            const float v0 = vr[row0], v1 = vr[row1];
#pragma unroll
            for (int nf = 0; nf < 4; nf++) {
                const int col = bn + wn * 32 + nf * 8 + 2 * t;
                float e00 = __expf(alpha * acc[mf][nf][0] + v0);
                float e01 = __expf(alpha * acc[mf][nf][1] + v0);
                float e10 = __expf(alpha * acc[mf][nf][2] + v1);
                float e11 = __expf(alpha * acc[mf][nf][3] + v1);
                *(__half2*)(Cb + (size_t)row0 * N + col) =
                    __floats2half2_rn(e00, e01);
                *(__half2*)(Cb + (size_t)row1 * N + col) =
                    __floats2half2_rn(e10, e11);
                cs[nf * 2 + 0] += e00 + e10;
                cs[nf * 2 + 1] += e01 + e11;
            }
        }
        float* red = (float*)sm;  // 256 floats
#pragma unroll
        for (int j = 0; j < 8; j++) {
#pragma unroll
            for (int o = 4; o <= 16; o <<= 1)
                cs[j] += __shfl_xor_sync(0xFFFFFFFFu, cs[j], o);
        }
        if (lane < 4) {
#pragma unroll
            for (int nf = 0; nf < 4; nf++) {
                red[wm * 128 + wn * 32 + nf * 8 + 2 * t + 0] = cs[nf * 2 + 0];
                red[wm * 128 + wn * 32 + nf * 8 + 2 * t + 1] = cs[nf * 2 + 1];
            }
        }
        __syncthreads();
        if (tid < 128) {
            g_part[((zz * 16) + blockIdx.y) * QLEN + bn + tid] =
                red[tid] + red[128 + tid];
        }
    } else {
#pragma unroll
        for (int mf = 0; mf < 4; mf++) {
            const int row0 = bm + wm * 64 + mf * 16 + g;
            const int row1 = row0 + 8;
            float s0 = 1.0f, s1 = 1.0f;
            if (rowsc != nullptr) {
                s0 = rowsc[zz * M + row0];
                s1 = rowsc[zz * M + row1];
            }
#pragma unroll
            for (int nf = 0; nf < 4; nf++) {
                const int col = bn + wn * 32 + nf * 8 + 2 * t;
                float bx = 0.0f, by = 0.0f;
                if (bias != nullptr) { bx = bias[col]; by = bias[col + 1]; }
                float o0x = s0 * (alpha * acc[mf][nf][0]) + bx;
                float o0y = s0 * (alpha * acc[mf][nf][1]) + by;
                float o1x = s1 * (alpha * acc[mf][nf][2]) + bx;
                float o1y = s1 * (alpha * acc[mf][nf][3]) + by;
                if (EPI == 0) {
                    float* Cb = Cf + zz * sC;
                    *(float2*)(Cb + (size_t)row0 * N + col) = make_float2(o0x, o0y);
                    *(float2*)(Cb + (size_t)row1 * N + col) = make_float2(o1x, o1y);
                } else {
                    __half* Cb = Ch + zz * sC;
                    *(__half2*)(Cb + (size_t)row0 * N + col) =
                        __floats2half2_rn(o0x, o0y);
                    *(__half2*)(Cb + (size_t)row1 * N + col) =
                        __floats2half2_rn(o1x, o1y);
                }
            }
        }
    }
}

// ---------------- instantiations ----------------
// Mt with 4-way k-split: blockIdx.z picks the K chunk; f32 partials out.
extern "C" __global__ void __launch_bounds__(256)
k_mt4()
{
    gbody<true, true, true, 0, 2, 1>(
        g_Wqh, g_Wql, g_Wkh, g_Wkl, g_MtP, nullptr, nullptr, nullptr,
        HID, HID, HID / 4, HID, HID, 32.0f,
        (size_t)(HID / 4) * HID,
        (size_t)(HID / 4) * HID,
        (size_t)HID * HID,
        blockIdx.z);
}

// reduce 4 Mt partials -> half
extern "C" __global__ void __launch_bounds__(256)
mt_red_k()
{
    const int i = blockIdx.x * 256 + threadIdx.x;   // float4 index
    const float4* p = (const float4*)g_MtP;
    const int n4 = (HID * HID) / 4;
    float4 s = p[i];
#pragma unroll
    for (int j = 1; j < 4; j++) {
        float4 t = p[i + j * n4];
        s.x += t.x; s.y += t.y; s.z += t.z; s.w += t.w;
    }
    __half2 h0 = __floats2half2_rn(s.x, s.y);
    __half2 h1 = __floats2half2_rn(s.z, s.w);
    ((uint2*)g_Mth)[i] = make_uint2(*(uint32_t*)&h0, *(uint32_t*)&h1);
}

// merged Vp + KM: blockIdx.z selects the problem (GROUP=2: half the barriers)
extern "C" __global__ void __launch_bounds__(256, 2)
k_proj2(const float* bv)
{
    if (blockIdx.z == 0)
        gbody<false, false, false, 1, 2, 2>(
            g_Vh, nullptr, g_Wvh, nullptr, nullptr, g_Vph, bv, nullptr,
            BNUM * SLEN, HID, HID, HID, HID, 1.0f, 0, 0, 0, 0);
    else
        gbody<false, false, false, 1, 2, 2>(
            g_Kh, nullptr, g_Mth, nullptr, nullptr, g_KMh, nullptr, nullptr,
            BNUM * SLEN, HID, HID, HID, HID, 0.03125f, 0, 0, 0, 0);
}

extern "C" __global__ void __launch_bounds__(256, 2)
k_sc(const __half* Ah, const __half* Bh, __half* Ch,
     int M, int N, int K, float alpha, size_t sA, size_t sB, size_t sC)
{ gbody<false, false, false, 2, 2, 2>(Ah, nullptr, Bh, nullptr, nullptr, Ch,
                                      nullptr, nullptr, M, N, K, K, K, alpha,
                                      sA, sB, sC, blockIdx.z); }

// merged ctx GEMM (z<8) + attn normalization (z>=8)
extern "C" __global__ void __launch_bounds__(256, 2)
k_ctxn(float* __restrict__ ctx, float* __restrict__ attn)
{
    if (blockIdx.z < 8) {
        gbody<true, false, false, 0, 2, 2>(
            g_Ph, nullptr, g_Vph, nullptr, ctx, nullptr, nullptr, g_inv,
            QLEN, HID, SLEN, QLEN, HID, 1.0f,
            (size_t)SLEN * QLEN, (size_t)SLEN * HID, (size_t)QLEN * HID,
            blockIdx.z);
    } else {
        // norm: attn[b,s,q] = Ph[b,s,q] * inv[b,q]
        const int cid = ((int)blockIdx.z - 8) * 128 + blockIdx.y * 8 + blockIdx.x;
        const uint2* ph4 = (const uint2*)g_Ph;
        float4* out = (float4*)attn;
        const int base = cid * 8192 + threadIdx.x;
#pragma unroll 4
        for (int j = 0; j < 32; j++) {
            const int i = base + j * 256;
            uint2 u = ph4[i];
            const int e0 = i * 4;
            const int q  = e0 & (QLEN - 1);
            const int b  = e0 >> 22;
            float4 inv = *(const float4*)(g_inv + ((size_t)b << 11) + q);
            __half2 h0 = *(__half2*)&u.x;
            __half2 h1 = *(__half2*)&u.y;
            float2 f0 = __half22float2(h0), f1 = __half22float2(h1);
            float4 o;
            o.x = f0.x * inv.x; o.y = f0.y * inv.y;
            o.z = f1.x * inv.z; o.w = f1.y * inv.w;
            out[i] = o;
        }
    }
}

// ---------------- f32 -> half conversions ----------------
extern "C" __global__ void __launch_bounds__(256)
cvtw_k(const float4* __restrict__ Wq, const float4* __restrict__ Wk,
       const float4* __restrict__ Wv)
{
    const int n4 = (HID * HID) / 4;
    const int z = blockIdx.z;
    const float4* in = (z == 0) ? Wq : (z == 1) ? Wk : Wv;
    uint2* hi = (z == 0) ? (uint2*)g_Wqh : (z == 1) ? (uint2*)g_Wkh
                                                    : (uint2*)g_Wvh;
    uint2* lo = (z == 0) ? (uint2*)g_Wql : (uint2*)g_Wkl;
    for (int i = blockIdx.x * 256 + threadIdx.x; i < n4; i += gridDim.x * 256) {
        float4 v = in[i];
        __half2 h0 = __floats2half2_rn(v.x, v.y);
        __half2 h1 = __floats2half2_rn(v.z, v.w);
        hi[i] = make_uint2(*(uint32_t*)&h0, *(uint32_t*)&h1);
        if (z < 2) {
            float2 f0 = __half22float2(h0), f1 = __half22float2(h1);
            __half2 l0 = __floats2half2_rn(v.x - f0.x, v.y - f0.y);
            __half2 l1 = __floats2half2_rn(v.z - f1.x, v.w - f1.y);
            lo[i] = make_uint2(*(uint32_t*)&l0, *(uint32_t*)&l1);
        }
    }
}
extern "C" __global__ void __launch_bounds__(256)
cvt3_k(const float4* __restrict__ q, const float4* __restrict__ k,
       const float4* __restrict__ v, int n4)
{
    const float4* in = (blockIdx.z == 0) ? q : (blockIdx.z == 1) ? k : v;
    uint2* out = (blockIdx.z == 0) ? (uint2*)g_Qh
               : (blockIdx.z == 1) ? (uint2*)g_Kh : (uint2*)g_Vh;
    for (int i = blockIdx.x * 256 + threadIdx.x; i < n4; i += gridDim.x * 256) {
        float4 x = in[i];
        __half2 h0 = __floats2half2_rn(x.x, x.y);
        __half2 h1 = __floats2half2_rn(x.z, x.w);
        out[i] = make_uint2(*(uint32_t*)&h0, *(uint32_t*)&h1);
    }
}

// ---------------- bias rank-1 correction (general-bq path) ----------------
__global__ void __launch_bounds__(256)
veca_k(const float* __restrict__ Wk, const float* __restrict__ bq)
{
    int any = 0;
    for (int i = threadIdx.x; i < HID; i += 256) any |= (bq[i] != 0.0f);
    const int r = __syncthreads_or(any);
    if (threadIdx.x == 0 && blockIdx.x == 0) g_flag = r ? 1 : 0;

    const int i = blockIdx.x * 256 + threadIdx.x;
    float s = 0.0f;
    if (r) {
        for (int o = 0; o < HID; o++) s += Wk[(size_t)o * HID + i] * bq[o];
    }
    g_vec[i] = s;
}
__global__ void __launch_bounds__(256)
vrow_k(const float* __restrict__ keys)
{
    const int r = blockIdx.x * 256 + threadIdx.x;
    float s = 0.0f;
    if (g_flag) {
        const float* kr = keys + (size_t)r * HID;
        for (int i = 0; i < HID; i++) s += kr[i] * g_vec[i];
    }
    g_vrow[r] = s;
}

// ---------------- per-q inverse sums ----------------
__global__ void __launch_bounds__(256) inv_k()
{
    const int i = blockIdx.x * 256 + threadIdx.x;   // b*QLEN + q
    const int b = i >> 11, q = i & (QLEN - 1);
    float tot = 0.0f;
#pragma unroll
    for (int j = 0; j < 16; j++)
        tot += g_part[((size_t)b * 16 + j) * QLEN + q];
    g_inv[i] = 1.0f / tot;
}

// ---------------- launcher (exact R11 topology) ----------------
extern "C" void kernel_launch(void* const* d_in, const int* in_sizes, int n_in,
                              void* d_out, int out_size)
{
    const float* queries = (const float*)d_in[0];
    const float* keys    = (const float*)d_in[1];
    const float* values  = (const float*)d_in[2];
    const float* Wq      = (const float*)d_in[3];
    const float* bq      = (const float*)d_in[4];
    const float* Wk      = (const float*)d_in[5];
    // d_in[6] = bk: enters scores only via per-q constants -> cancels in softmax
    const float* Wv      = (const float*)d_in[7];
    const float* bv      = (const float*)d_in[8];

    float* ctx  = (float*)d_out;                                // [B,Q,H]
    float* attn = (float*)d_out + (size_t)BNUM * QLEN * HID;    // [B,S,Q]

    __half *qh, *kmh, *ph;
    cudaGetSymbolAddress((void**)&qh, g_Qh);
    cudaGetSymbolAddress((void**)&kmh, g_KMh);
    cudaGetSymbolAddress((void**)&ph, g_Ph);

    static cudaStream_t s1 = nullptr;
    static cudaEvent_t  evFork = nullptr, evJoin = nullptr;
    static bool init_done = false;
    if (!init_done) {
        cudaStreamCreateWithFlags(&s1, cudaStreamNonBlocking);
        cudaEventCreateWithFlags(&evFork, cudaEventDisableTiming);
        cudaEventCreateWithFlags(&evJoin, cudaEventDisableTiming);
        cudaFuncSetAttribute(k_mt4,   cudaFuncAttributeMaxDynamicSharedMemorySize, 2 * 4 * SLOT);
        cudaFuncSetAttribute(k_proj2, cudaFuncAttributeMaxDynamicSharedMemorySize, 2 * 2 * 2 * SLOT);
        cudaFuncSetAttribute(k_sc,    cudaFuncAttributeMaxDynamicSharedMemorySize, 2 * 2 * 2 * SLOT);
        cudaFuncSetAttribute(k_ctxn,  cudaFuncAttributeMaxDynamicSharedMemorySize, 2 * 2 * 2 * SLOT);
        init_done = true;
    }

    const int nBig4 = (BNUM * SLEN * HID) / 4;

    // ---- fork: weight-conversion + Mt chain on side stream s1 ----
    cudaEventRecord(evFork, 0);
    cudaStreamWaitEvent(s1, evFork, 0);
    cvtw_k<<<dim3(256, 1, 3), 256, 0, s1>>>((const float4*)Wq,
                                            (const float4*)Wk,
                                            (const float4*)Wv);
    k_mt4<<<dim3(8, 8, 4), 256, 2 * 4 * SLOT, s1>>>();
    mt_red_k<<<(HID * HID / 4) / 256, 256, 0, s1>>>();
    cudaEventRecord(evJoin, s1);

    // ---- main stream: bias chain + activation conversions (overlaps s1) ----
    veca_k<<<HID / 256, 256>>>(Wk, bq);
    vrow_k<<<(BNUM * SLEN) / 256, 256>>>(keys);
    cvt3_k<<<dim3(2048, 1, 3), 256>>>((const float4*)queries,
                                      (const float4*)keys,
                                      (const float4*)values, nBig4);

    // ---- join: everything below needs both tracks ----
    cudaStreamWaitEvent(0, evJoin, 0);

    // merged Vp (z=0) and KM (z=1)
    k_proj2<<<dim3(HID / TN, (BNUM * SLEN) / TM, 2), 256, 2 * 2 * 2 * SLOT>>>(bv);

    // Ph[b,s,q] = f16(exp((1/32)*KM.q + vrow)) + col-sum partials
    k_sc<<<dim3(QLEN / TN, SLEN / TM, BNUM), 256, 2 * 2 * 2 * SLOT>>>(
        kmh, qh, ph, SLEN, QLEN, HID, 0.03125f,
        (size_t)SLEN * HID, (size_t)QLEN * HID, (size_t)SLEN * QLEN);

    // per-q inverse sums
    inv_k<<<(BNUM * QLEN) / 256, 256>>>();

    // merged: ctx GEMM (z<8, row-scaled by inv) + attn normalization (z>=8)
    k_ctxn<<<dim3(HID / TN, QLEN / TM, 16), 256, 2 * 2 * 2 * SLOT>>>(ctx, attn);
}

// round 15
// speedup vs baseline: 1.0215x; 1.0215x over previous
#include <cuda_runtime.h>
#include <cuda_fp16.h>
#include <cstdint>

#define HID   1024
#define BNUM  8
#define SLEN  2048
#define QLEN  2048

// ---------------- scratch: fp16 operand planes (allocation-free) -----------
__device__ __half g_Qh[(size_t)BNUM * QLEN * HID];
__device__ __half g_Kh[(size_t)BNUM * SLEN * HID];
__device__ __half g_Vh[(size_t)BNUM * SLEN * HID];
__device__ __half g_Wqh[(size_t)HID * HID];
__device__ __half g_Wql[(size_t)HID * HID];
__device__ __half g_Wkh[(size_t)HID * HID];
__device__ __half g_Wkl[(size_t)HID * HID];
__device__ __half g_Wvh[(size_t)HID * HID];
__device__ __half g_Mth[(size_t)HID * HID];          // 32 * Wq^T Wk (hi)
__device__ float  g_MtP[(size_t)4 * HID * HID];      // Mt k-split partials
__device__ __half g_KMh[(size_t)BNUM * SLEN * HID];  // keys*M (hi)
__device__ __half g_Vph[(size_t)BNUM * SLEN * HID];  // V proj (hi)
__device__ __half g_Ph [(size_t)BNUM * SLEN * QLEN]; // exp(scores) f16 (unnorm)
__device__ float  g_part[(size_t)BNUM * 16 * QLEN];  // col-sum partials
__device__ float  g_inv [(size_t)BNUM * QLEN];       // 1 / col sums
__device__ float  g_vrow[(size_t)BNUM * SLEN];       // keys * (Wk^T bq)
__device__ float  g_vec[HID];
__device__ int    g_flag;

// ---------------- geometry ----------------
#define TM   128
#define TN   128
#define TKF  32
#define SLOT 10240         // one plane-tile slot (max of NT 10240 / TN 8704)
#define PNT  80            // NT tile row pitch (64B data + 16B pad)
#define PTR  272           // TRANS tile row pitch (256B data + 16B pad)

// ---------------- PTX helpers ----------------
__device__ __forceinline__ uint32_t smem_u32(const void* p) {
    uint32_t a;
    asm("{ .reg .u64 t; cvta.to.shared.u64 t, %1; cvt.u32.u64 %0, t; }"
        : "=r"(a) : "l"(p));
    return a;
}
__device__ __forceinline__ void cp16(uint32_t s, const void* g) {
    asm volatile("cp.async.cg.shared.global [%0], [%1], 16;"
                 :: "r"(s), "l"(g));
}
__device__ __forceinline__ void cp_commit() {
    asm volatile("cp.async.commit_group;" ::: "memory");
}
template <int N_>
__device__ __forceinline__ void cp_wait() {
    asm volatile("cp.async.wait_group %0;" :: "n"(N_) : "memory");
}
__device__ __forceinline__ void ldsm4(uint32_t* r, uint32_t addr) {
    asm volatile("ldmatrix.sync.aligned.m8n8.x4.shared.b16 {%0,%1,%2,%3}, [%4];"
                 : "=r"(r[0]), "=r"(r[1]), "=r"(r[2]), "=r"(r[3]) : "r"(addr));
}
__device__ __forceinline__ void ldsm4t(uint32_t* r, uint32_t addr) {
    asm volatile("ldmatrix.sync.aligned.m8n8.x4.trans.shared.b16 {%0,%1,%2,%3}, [%4];"
                 : "=r"(r[0]), "=r"(r[1]), "=r"(r[2]), "=r"(r[3]) : "r"(addr));
}
__device__ __forceinline__ void mma16816(float* c, const uint32_t* a,
                                         const uint32_t* b) {
    asm volatile(
        "mma.sync.aligned.m16n8k16.row.col.f32.f16.f16.f32 "
        "{%0,%1,%2,%3}, {%4,%5,%6,%7}, {%8,%9}, {%0,%1,%2,%3};"
        : "+f"(c[0]), "+f"(c[1]), "+f"(c[2]), "+f"(c[3])
        : "r"(a[0]), "r"(a[1]), "r"(a[2]), "r"(a[3]), "r"(b[0]), "r"(b[1]));
}

// ---------------------------------------------------------------------------
// Unified fp16 tensor-core GEMM over pre-converted half planes.
// NT (TRANS=0): C[m,n] = alpha*sum_k A[m,k]*B[n,k], A:[M,K], B:[N,K]
// TN (TRANS=1): C[m,n] = alpha*sum_k A[k,m]*B[k,n], A:[K,M], B:[K,N]
// ASPL/BSPL: lo-residual planes (extra MMA each).
// EPI: 0 = f32 out (+bias) [optionally * rowsc[row]];
//      1 = half out (+bias);
//      2 = exp epilogue: writes f16 exp to Ch, col-sum partials to g_part.
// STAGES: cp.async pipeline depth (one __syncthreads per k-iter).
// ---------------------------------------------------------------------------
template <bool TRANS, bool ASPL, bool BSPL, int EPI, int STAGES>
__device__ __forceinline__ void gbody(
    const __half* __restrict__ Ah, const __half* __restrict__ Al,
    const __half* __restrict__ Bh, const __half* __restrict__ Bl,
    float* __restrict__ Cf, __half* __restrict__ Ch,
    const float* __restrict__ bias, const float* __restrict__ rowsc,
    int M, int N, int K, int ldA, int ldB, float alpha,
    size_t sA, size_t sB, size_t sC, int zz_in)
{
    constexpr int NPA = ASPL ? 2 : 1;
    constexpr int NP  = NPA + (BSPL ? 2 : 1);
    constexpr int STG = NP * SLOT;

    extern __shared__ char sm[];
    const uint32_t sb = smem_u32(sm);

    const int tid  = threadIdx.x;
    const int lane = tid & 31;
    const int w    = tid >> 5;
    const int wm   = w & 1;
    const int wn   = w >> 1;
    const int g    = lane >> 2;
    const int t    = lane & 3;

    const size_t zz = zz_in;
    const __half* Ahb = Ah + zz * sA;
    const __half* Alb = ASPL ? Al + zz * sA : nullptr;
    const __half* Bhb = Bh + zz * sB;
    const __half* Blb = BSPL ? Bl + zz * sB : nullptr;
    const int bm = blockIdx.y * TM;
    const int bn = blockIdx.x * TN;

    // fragment address components
    const int a_r   = ((lane >> 3) & 1) * 8 + (lane & 7);
    const int a_c8  = (lane >> 4) * 8;
    const int b_r   = (lane >> 4) * 8 + (lane & 7);
    const int b_c8  = ((lane >> 3) & 1) * 8;
    const int at_r  = (lane >> 4) * 8 + (lane & 7);
    const int at_c8 = ((lane >> 3) & 1) * 8;
    const int bt_r  = ((lane >> 3) & 1) * 8 + (lane & 7);
    const int bt_c8 = (lane >> 4) * 8;

    float acc[4][4][4];
#pragma unroll
    for (int i = 0; i < 4; i++)
#pragma unroll
        for (int j = 0; j < 4; j++)
#pragma unroll
            for (int e = 0; e < 4; e++) acc[i][j][e] = 0.0f;

    const int NK = K / TKF;

    auto issue = [&](int kt, int p) {
        const uint32_t st = sb + p * STG;
        if (!TRANS) {
#pragma unroll
            for (int j = 0; j < 2; j++) {
                const int idx = tid * 2 + j;
                const int r = idx >> 2, c = idx & 3;
                const uint32_t so = (uint32_t)(r * PNT + c * 16);
                const size_t goA = (size_t)(bm + r) * ldA + kt * TKF + c * 8;
                const size_t goB = (size_t)(bn + r) * ldB + kt * TKF + c * 8;
                cp16(st + so, Ahb + goA);
                if (ASPL) cp16(st + SLOT + so, Alb + goA);
                cp16(st + NPA * SLOT + so, Bhb + goB);
                if (BSPL) cp16(st + (NPA + 1) * SLOT + so, Blb + goB);
            }
        } else {
#pragma unroll
            for (int j = 0; j < 2; j++) {
                const int idx = tid * 2 + j;
                const int r = idx >> 4, c = idx & 15;
                const uint32_t so = (uint32_t)(r * PTR + c * 16);
                const size_t goA = (size_t)(kt * TKF + r) * ldA + bm + c * 8;
                const size_t goB = (size_t)(kt * TKF + r) * ldB + bn + c * 8;
                cp16(st + so, Ahb + goA);
                if (ASPL) cp16(st + SLOT + so, Alb + goA);
                cp16(st + NPA * SLOT + so, Bhb + goB);
                if (BSPL) cp16(st + (NPA + 1) * SLOT + so, Blb + goB);
            }
        }
    };

    // prologue: fill STAGES-1 buffers, one commit group per tile
#pragma unroll
    for (int s = 0; s < STAGES - 1; s++) {
        if (s < NK) issue(s, s);
        cp_commit();
    }

    for (int kt = 0; kt < NK; kt++) {
        const int p = kt % STAGES;

        cp_wait<STAGES - 2>();   // tile kt resident
        __syncthreads();         // also guards reuse of buffer being refilled

        if (kt + STAGES - 1 < NK) issue(kt + STAGES - 1, (kt + STAGES - 1) % STAGES);
        cp_commit();             // keep group numbering aligned (may be empty)

        const uint32_t sa_hi = sb + p * STG;
        const uint32_t sa_lo = sa_hi + SLOT;
        const uint32_t sb_hi = sa_hi + NPA * SLOT;
        const uint32_t sb_lo = sb_hi + SLOT;

#pragma unroll
        for (int ks = 0; ks < 2; ks++) {
            const int k0 = ks * 16;

            uint32_t bh[8], bl[8];
#pragma unroll
            for (int j = 0; j < 2; j++) {
                uint32_t addr;
                if (!TRANS) {
                    addr = (uint32_t)((wn * 32 + j * 16 + b_r) * PNT +
                                      (k0 + b_c8) * 2);
                    ldsm4(bh + 4 * j, sb_hi + addr);
                    if (BSPL) ldsm4(bl + 4 * j, sb_lo + addr);
                } else {
                    addr = (uint32_t)((k0 + bt_r) * PTR +
                                      (wn * 32 + j * 16 + bt_c8) * 2);
                    ldsm4t(bh + 4 * j, sb_hi + addr);
                    if (BSPL) ldsm4t(bl + 4 * j, sb_lo + addr);
                }
            }

            uint32_t ah[4][4], al[4][4];
#pragma unroll
            for (int mf = 0; mf < 4; mf++) {
                uint32_t addr;
                if (!TRANS) {
                    addr = (uint32_t)((wm * 64 + mf * 16 + a_r) * PNT +
                                      (k0 + a_c8) * 2);
                    ldsm4(ah[mf], sa_hi + addr);
                    if (ASPL) ldsm4(al[mf], sa_lo + addr);
                } else {
                    addr = (uint32_t)((k0 + at_r) * PTR +
                                      (wm * 64 + mf * 16 + at_c8) * 2);
                    ldsm4t(ah[mf], sa_hi + addr);
                    if (ASPL) ldsm4t(al[mf], sa_lo + addr);
                }
            }

#pragma unroll
            for (int mf = 0; mf < 4; mf++)
#pragma unroll
                for (int nf = 0; nf < 4; nf++) {
                    mma16816(acc[mf][nf], ah[mf], bh + 2 * nf);
                    if (ASPL) mma16816(acc[mf][nf], al[mf], bh + 2 * nf);
                    if (BSPL) mma16816(acc[mf][nf], ah[mf], bl + 2 * nf);
                }
        }
        // no trailing sync: next iteration's sync (after cp_wait) guards reuse
    }

    // ---------------- epilogues ----------------
    if (EPI == 2) {
        __syncthreads();  // smem 'red' reuses pipeline buffers
        __half* Cb = Ch + zz * sC;
        const float* vr = g_vrow + zz * SLEN;
        float cs[8];
#pragma unroll
        for (int j = 0; j < 8; j++) cs[j] = 0.0f;

#pragma unroll
        for (int mf = 0; mf < 4; mf++) {
            const int row0 = bm + wm * 64 + mf * 16 + g;
            const int row1 = row0 + 8;
            const float v0 = vr[row0], v1 = vr[row1];
#pragma unroll
            for (int nf = 0; nf < 4; nf++) {
                const int col = bn + wn * 32 + nf * 8 + 2 * t;
                float e00 = __expf(alpha * acc[mf][nf][0] + v0);
                float e01 = __expf(alpha * acc[mf][nf][1] + v0);
                float e10 = __expf(alpha * acc[mf][nf][2] + v1);
                float e11 = __expf(alpha * acc[mf][nf][3] + v1);
                *(__half2*)(Cb + (size_t)row0 * N + col) =
                    __floats2half2_rn(e00, e01);
                *(__half2*)(Cb + (size_t)row1 * N + col) =
                    __floats2half2_rn(e10, e11);
                cs[nf * 2 + 0] += e00 + e10;
                cs[nf * 2 + 1] += e01 + e11;
            }
        }
        float* red = (float*)sm;  // 256 floats
#pragma unroll
        for (int j = 0; j < 8; j++) {
#pragma unroll
            for (int o = 4; o <= 16; o <<= 1)
                cs[j] += __shfl_xor_sync(0xFFFFFFFFu, cs[j], o);
        }
        if (lane < 4) {
#pragma unroll
            for (int nf = 0; nf < 4; nf++) {
                red[wm * 128 + wn * 32 + nf * 8 + 2 * t + 0] = cs[nf * 2 + 0];
                red[wm * 128 + wn * 32 + nf * 8 + 2 * t + 1] = cs[nf * 2 + 1];
            }
        }
        __syncthreads();
        if (tid < 128) {
            g_part[((zz * 16) + blockIdx.y) * QLEN + bn + tid] =
                red[tid] + red[128 + tid];
        }
    } else {
#pragma unroll
        for (int mf = 0; mf < 4; mf++) {
            const int row0 = bm + wm * 64 + mf * 16 + g;
            const int row1 = row0 + 8;
            float s0 = 1.0f, s1 = 1.0f;
            if (rowsc != nullptr) {
                s0 = rowsc[zz * M + row0];
                s1 = rowsc[zz * M + row1];
            }
#pragma unroll
            for (int nf = 0; nf < 4; nf++) {
                const int col = bn + wn * 32 + nf * 8 + 2 * t;
                float bx = 0.0f, by = 0.0f;
                if (bias != nullptr) { bx = bias[col]; by = bias[col + 1]; }
                float o0x = s0 * (alpha * acc[mf][nf][0]) + bx;
                float o0y = s0 * (alpha * acc[mf][nf][1]) + by;
                float o1x = s1 * (alpha * acc[mf][nf][2]) + bx;
                float o1y = s1 * (alpha * acc[mf][nf][3]) + by;
                if (EPI == 0) {
                    float* Cb = Cf + zz * sC;
                    *(float2*)(Cb + (size_t)row0 * N + col) = make_float2(o0x, o0y);
                    *(float2*)(Cb + (size_t)row1 * N + col) = make_float2(o1x, o1y);
                } else {
                    __half* Cb = Ch + zz * sC;
                    *(__half2*)(Cb + (size_t)row0 * N + col) =
                        __floats2half2_rn(o0x, o0y);
                    *(__half2*)(Cb + (size_t)row1 * N + col) =
                        __floats2half2_rn(o1x, o1y);
                }
            }
        }
    }
}

// ---------------- instantiations ----------------
// Mt with 4-way k-split: blockIdx.z picks the K chunk; f32 partials out.
extern "C" __global__ void __launch_bounds__(256)
k_mt4()
{
    gbody<true, true, true, 0, 2>(
        g_Wqh, g_Wql, g_Wkh, g_Wkl, g_MtP, nullptr, nullptr, nullptr,
        HID, HID, HID / 4, HID, HID, 32.0f,
        (size_t)(HID / 4) * HID,      // A k-chunk offset ([K,M] row-major)
        (size_t)(HID / 4) * HID,      // B k-chunk offset
        (size_t)HID * HID,            // partial-buffer stride
        blockIdx.z);
}

// reduce 4 Mt partials -> half
extern "C" __global__ void __launch_bounds__(256)
mt_red_k()
{
    const int i = blockIdx.x * 256 + threadIdx.x;   // float4 index, 262144 total
    const float4* p = (const float4*)g_MtP;
    const int n4 = (HID * HID) / 4;
    float4 s = p[i];
#pragma unroll
    for (int j = 1; j < 4; j++) {
        float4 t = p[i + j * n4];
        s.x += t.x; s.y += t.y; s.z += t.z; s.w += t.w;
    }
    __half2 h0 = __floats2half2_rn(s.x, s.y);
    __half2 h1 = __floats2half2_rn(s.z, s.w);
    ((uint2*)g_Mth)[i] = make_uint2(*(uint32_t*)&h0, *(uint32_t*)&h1);
}

// merged Vp + KM: blockIdx.z selects the problem
extern "C" __global__ void __launch_bounds__(256, 2)
k_proj2(const float* bv)
{
    if (blockIdx.z == 0)
        gbody<false, false, false, 1, 4>(
            g_Vh, nullptr, g_Wvh, nullptr, nullptr, g_Vph, bv, nullptr,
            BNUM * SLEN, HID, HID, HID, HID, 1.0f, 0, 0, 0, 0);
    else
        gbody<false, false, false, 1, 4>(
            g_Kh, nullptr, g_Mth, nullptr, nullptr, g_KMh, nullptr, nullptr,
            BNUM * SLEN, HID, HID, HID, HID, 0.03125f, 0, 0, 0, 0);
}

extern "C" __global__ void __launch_bounds__(256, 2)
k_sc(const __half* Ah, const __half* Bh, __half* Ch,
     int M, int N, int K, float alpha, size_t sA, size_t sB, size_t sC)
{ gbody<false, false, false, 2, 4>(Ah, nullptr, Bh, nullptr, nullptr, Ch,
                                   nullptr, nullptr, M, N, K, K, K, alpha,
                                   sA, sB, sC, blockIdx.z); }

// merged ctx GEMM (z<8) + attn normalization (z>=8)
extern "C" __global__ void __launch_bounds__(256, 2)
k_ctxn(float* __restrict__ ctx, float* __restrict__ attn)
{
    if (blockIdx.z < 8) {
        gbody<true, false, false, 0, 4>(
            g_Ph, nullptr, g_Vph, nullptr, ctx, nullptr, nullptr, g_inv,
            QLEN, HID, SLEN, QLEN, HID, 1.0f,
            (size_t)SLEN * QLEN, (size_t)SLEN * HID, (size_t)QLEN * HID,
            blockIdx.z);
    } else {
        // norm: attn[b,s,q] = Ph[b,s,q] * inv[b,q]
        const int cid = ((int)blockIdx.z - 8) * 128 + blockIdx.y * 8 + blockIdx.x;
        const uint2* ph4 = (const uint2*)g_Ph;
        float4* out = (float4*)attn;
        const int base = cid * 8192 + threadIdx.x;   // 1024 CTAs * 8192 f4
#pragma unroll 4
        for (int j = 0; j < 32; j++) {
            const int i = base + j * 256;
            uint2 u = ph4[i];
            const int e0 = i * 4;
            const int q  = e0 & (QLEN - 1);
            const int b  = e0 >> 22;
            float4 inv = *(const float4*)(g_inv + ((size_t)b << 11) + q);
            __half2 h0 = *(__half2*)&u.x;
            __half2 h1 = *(__half2*)&u.y;
            float2 f0 = __half22float2(h0), f1 = __half22float2(h1);
            float4 o;
            o.x = f0.x * inv.x; o.y = f0.y * inv.y;
            o.z = f1.x * inv.z; o.w = f1.y * inv.w;
            out[i] = o;
        }
    }
}

// ---------------- f32 -> half conversions ----------------
// merged weight conversion: z=0 Wq(split), z=1 Wk(split), z=2 Wv(hi)
extern "C" __global__ void __launch_bounds__(256)
cvtw_k(const float4* __restrict__ Wq, const float4* __restrict__ Wk,
       const float4* __restrict__ Wv)
{
    const int n4 = (HID * HID) / 4;
    const int z = blockIdx.z;
    const float4* in = (z == 0) ? Wq : (z == 1) ? Wk : Wv;
    uint2* hi = (z == 0) ? (uint2*)g_Wqh : (z == 1) ? (uint2*)g_Wkh
                                                    : (uint2*)g_Wvh;
    uint2* lo = (z == 0) ? (uint2*)g_Wql : (uint2*)g_Wkl;
    for (int i = blockIdx.x * 256 + threadIdx.x; i < n4; i += gridDim.x * 256) {
        float4 v = in[i];
        __half2 h0 = __floats2half2_rn(v.x, v.y);
        __half2 h1 = __floats2half2_rn(v.z, v.w);
        hi[i] = make_uint2(*(uint32_t*)&h0, *(uint32_t*)&h1);
        if (z < 2) {
            float2 f0 = __half22float2(h0), f1 = __half22float2(h1);
            __half2 l0 = __floats2half2_rn(v.x - f0.x, v.y - f0.y);
            __half2 l1 = __floats2half2_rn(v.z - f1.x, v.w - f1.y);
            lo[i] = make_uint2(*(uint32_t*)&l0, *(uint32_t*)&l1);
        }
    }
}
// merged q/k/v hi-conversion: blockIdx.z picks the tensor
extern "C" __global__ void __launch_bounds__(256)
cvt3_k(const float4* __restrict__ q, const float4* __restrict__ k,
       const float4* __restrict__ v, int n4)
{
    const float4* in = (blockIdx.z == 0) ? q : (blockIdx.z == 1) ? k : v;
    uint2* out = (blockIdx.z == 0) ? (uint2*)g_Qh
               : (blockIdx.z == 1) ? (uint2*)g_Kh : (uint2*)g_Vh;
    for (int i = blockIdx.x * 256 + threadIdx.x; i < n4; i += gridDim.x * 256) {
        float4 x = in[i];
        __half2 h0 = __floats2half2_rn(x.x, x.y);
        __half2 h1 = __floats2half2_rn(x.z, x.w);
        out[i] = make_uint2(*(uint32_t*)&h0, *(uint32_t*)&h1);
    }
}

// ---------------- bias rank-1 correction (general-bq path) ----------------
__global__ void __launch_bounds__(256)
veca_k(const float* __restrict__ Wk, const float* __restrict__ bq)
{
    int any = 0;
    for (int i = threadIdx.x; i < HID; i += 256) any |= (bq[i] != 0.0f);
    const int r = __syncthreads_or(any);
    if (threadIdx.x == 0 && blockIdx.x == 0) g_flag = r ? 1 : 0;

    const int i = blockIdx.x * 256 + threadIdx.x;
    float s = 0.0f;
    if (r) {
        for (int o = 0; o < HID; o++) s += Wk[(size_t)o * HID + i] * bq[o];
    }
    g_vec[i] = s;
}
__global__ void __launch_bounds__(256)
vrow_k(const float* __restrict__ keys)
{
    const int r = blockIdx.x * 256 + threadIdx.x;
    float s = 0.0f;
    if (g_flag) {
        const float* kr = keys + (size_t)r * HID;
        for (int i = 0; i < HID; i++) s += kr[i] * g_vec[i];
    }
    g_vrow[r] = s;
}

// ---------------- per-q inverse sums ----------------
__global__ void __launch_bounds__(256) inv_k()
{
    const int i = blockIdx.x * 256 + threadIdx.x;   // b*QLEN + q
    const int b = i >> 11, q = i & (QLEN - 1);
    float tot = 0.0f;
#pragma unroll
    for (int j = 0; j < 16; j++)
        tot += g_part[((size_t)b * 16 + j) * QLEN + q];
    g_inv[i] = 1.0f / tot;
}

// ---------------- launcher (R11 topology, best measured: 828.4 us) --------
extern "C" void kernel_launch(void* const* d_in, const int* in_sizes, int n_in,
                              void* d_out, int out_size)
{
    const float* queries = (const float*)d_in[0];
    const float* keys    = (const float*)d_in[1];
    const float* values  = (const float*)d_in[2];
    const float* Wq      = (const float*)d_in[3];
    const float* bq      = (const float*)d_in[4];
    const float* Wk      = (const float*)d_in[5];
    // d_in[6] = bk: enters scores only via per-q constants -> cancels in softmax
    const float* Wv      = (const float*)d_in[7];
    const float* bv      = (const float*)d_in[8];

    float* ctx  = (float*)d_out;                                // [B,Q,H]
    float* attn = (float*)d_out + (size_t)BNUM * QLEN * HID;    // [B,S,Q]

    __half *qh, *kmh, *ph;
    cudaGetSymbolAddress((void**)&qh, g_Qh);
    cudaGetSymbolAddress((void**)&kmh, g_KMh);
    cudaGetSymbolAddress((void**)&ph, g_Ph);

    static cudaStream_t s1 = nullptr;
    static cudaEvent_t  evFork = nullptr, evJoin = nullptr;
    static bool init_done = false;
    if (!init_done) {
        cudaStreamCreateWithFlags(&s1, cudaStreamNonBlocking);
        cudaEventCreateWithFlags(&evFork, cudaEventDisableTiming);
        cudaEventCreateWithFlags(&evJoin, cudaEventDisableTiming);
        cudaFuncSetAttribute(k_mt4,   cudaFuncAttributeMaxDynamicSharedMemorySize, 2 * 4 * SLOT);
        cudaFuncSetAttribute(k_proj2, cudaFuncAttributeMaxDynamicSharedMemorySize, 4 * 2 * SLOT);
        cudaFuncSetAttribute(k_sc,    cudaFuncAttributeMaxDynamicSharedMemorySize, 4 * 2 * SLOT);
        cudaFuncSetAttribute(k_ctxn,  cudaFuncAttributeMaxDynamicSharedMemorySize, 4 * 2 * SLOT);
        init_done = true;
    }

    const int nBig4 = (BNUM * SLEN * HID) / 4;

    // ---- fork: weight-conversion + Mt chain on side stream s1 ----
    cudaEventRecord(evFork, 0);
    cudaStreamWaitEvent(s1, evFork, 0);
    cvtw_k<<<dim3(256, 1, 3), 256, 0, s1>>>((const float4*)Wq,
                                            (const float4*)Wk,
                                            (const float4*)Wv);
    k_mt4<<<dim3(8, 8, 4), 256, 2 * 4 * SLOT, s1>>>();
    mt_red_k<<<(HID * HID / 4) / 256, 256, 0, s1>>>();
    cudaEventRecord(evJoin, s1);

    // ---- main stream: bias chain + activation conversions (overlaps s1) ----
    veca_k<<<HID / 256, 256>>>(Wk, bq);
    vrow_k<<<(BNUM * SLEN) / 256, 256>>>(keys);
    cvt3_k<<<dim3(2048, 1, 3), 256>>>((const float4*)queries,
                                      (const float4*)keys,
                                      (const float4*)values, nBig4);

    // ---- join: everything below needs both tracks ----
    cudaStreamWaitEvent(0, evJoin, 0);

    // merged Vp (z=0) and KM (z=1)
    k_proj2<<<dim3(HID / TN, (BNUM * SLEN) / TM, 2), 256, 4 * 2 * SLOT>>>(bv);

    // Ph[b,s,q] = f16(exp((1/32)*KM.q + vrow)) + col-sum partials
    k_sc<<<dim3(QLEN / TN, SLEN / TM, BNUM), 256, 4 * 2 * SLOT>>>(
        kmh, qh, ph, SLEN, QLEN, HID, 0.03125f,
        (size_t)SLEN * HID, (size_t)QLEN * HID, (size_t)SLEN * QLEN);

    // per-q inverse sums
    inv_k<<<(BNUM * QLEN) / 256, 256>>>();

    // merged: ctx GEMM (z<8, row-scaled by inv) + attn normalization (z>=8)
    k_ctxn<<<dim3(HID / TN, QLEN / TM, 16), 256, 4 * 2 * SLOT>>>(ctx, attn);
}

// round 16
// speedup vs baseline: 1.0785x; 1.0558x over previous
#include <cuda_runtime.h>
#include <cuda_fp16.h>
#include <cstdint>

#define HID   1024
#define BNUM  8
#define SLEN  2048
#define QLEN  2048

// ---------------- scratch: fp16 operand planes (allocation-free) -----------
__device__ __half g_Qh[(size_t)BNUM * QLEN * HID];
__device__ __half g_Kh[(size_t)BNUM * SLEN * HID];
__device__ __half g_Vh[(size_t)BNUM * SLEN * HID];
__device__ __half g_Wqh[(size_t)HID * HID];
__device__ __half g_Wql[(size_t)HID * HID];
__device__ __half g_Wkh[(size_t)HID * HID];
__device__ __half g_Wkl[(size_t)HID * HID];
__device__ __half g_Wvh[(size_t)HID * HID];
__device__ __half g_Mth[(size_t)HID * HID];          // 32 * Wq^T Wk (hi)
__device__ float  g_MtP[(size_t)4 * HID * HID];      // Mt k-split partials
__device__ __half g_KMh[(size_t)BNUM * SLEN * HID];  // keys*M (hi)
__device__ __half g_Vph[(size_t)BNUM * SLEN * HID];  // V proj (hi)
__device__ __half g_Ph [(size_t)BNUM * SLEN * QLEN]; // exp(scores) f16 (unnorm)
__device__ float  g_part[(size_t)BNUM * 16 * QLEN];  // col-sum partials
__device__ float  g_inv [(size_t)BNUM * QLEN];       // 1 / col sums
__device__ float  g_vrow[(size_t)BNUM * SLEN];       // keys * (Wk^T bq)
__device__ float  g_vec[HID];
__device__ int    g_flag;

// ---------------- geometry ----------------
#define TM   128
#define TN   128
#define TKF  32
#define SLOT 10240         // one plane-tile slot (max of NT 10240 / TN 8704)
#define PNT  80            // NT tile row pitch (64B data + 16B pad)
#define PTR  272           // TRANS tile row pitch (256B data + 16B pad)

// ---------------- PTX helpers ----------------
__device__ __forceinline__ uint32_t smem_u32(const void* p) {
    uint32_t a;
    asm("{ .reg .u64 t; cvta.to.shared.u64 t, %1; cvt.u32.u64 %0, t; }"
        : "=r"(a) : "l"(p));
    return a;
}
__device__ __forceinline__ void cp16(uint32_t s, const void* g) {
    asm volatile("cp.async.cg.shared.global [%0], [%1], 16;"
                 :: "r"(s), "l"(g));
}
__device__ __forceinline__ void cp_commit() {
    asm volatile("cp.async.commit_group;" ::: "memory");
}
template <int N_>
__device__ __forceinline__ void cp_wait() {
    asm volatile("cp.async.wait_group %0;" :: "n"(N_) : "memory");
}
__device__ __forceinline__ void ldsm4(uint32_t* r, uint32_t addr) {
    asm volatile("ldmatrix.sync.aligned.m8n8.x4.shared.b16 {%0,%1,%2,%3}, [%4];"
                 : "=r"(r[0]), "=r"(r[1]), "=r"(r[2]), "=r"(r[3]) : "r"(addr));
}
__device__ __forceinline__ void ldsm4t(uint32_t* r, uint32_t addr) {
    asm volatile("ldmatrix.sync.aligned.m8n8.x4.trans.shared.b16 {%0,%1,%2,%3}, [%4];"
                 : "=r"(r[0]), "=r"(r[1]), "=r"(r[2]), "=r"(r[3]) : "r"(addr));
}
__device__ __forceinline__ void mma16816(float* c, const uint32_t* a,
                                         const uint32_t* b) {
    asm volatile(
        "mma.sync.aligned.m16n8k16.row.col.f32.f16.f16.f32 "
        "{%0,%1,%2,%3}, {%4,%5,%6,%7}, {%8,%9}, {%0,%1,%2,%3};"
        : "+f"(c[0]), "+f"(c[1]), "+f"(c[2]), "+f"(c[3])
        : "r"(a[0]), "r"(a[1]), "r"(a[2]), "r"(a[3]), "r"(b[0]), "r"(b[1]));
}

// ---------------------------------------------------------------------------
// Unified fp16 tensor-core GEMM over pre-converted half planes.
// NT (TRANS=0): C[m,n] = alpha*sum_k A[m,k]*B[n,k], A:[M,K], B:[N,K]
// TN (TRANS=1): C[m,n] = alpha*sum_k A[k,m]*B[k,n], A:[K,M], B:[K,N]
// ASPL/BSPL: lo-residual planes (extra MMA each).
// EPI: 0 = f32 out (+bias) [optionally * rowsc[row]];
//      1 = half out (+bias);
//      2 = exp epilogue: writes f16 exp to Ch, col-sum partials to g_part.
// STAGES: cp.async pipeline depth (one __syncthreads per k-iter).
// Refill issue happens AFTER the compute block: prefetched data has
// STAGES-1 iters of lead time, so the LDGSTS burst stays off the
// ldsm->MMA critical path (asm volatile prevents ptxas reordering).
// ---------------------------------------------------------------------------
template <bool TRANS, bool ASPL, bool BSPL, int EPI, int STAGES>
__device__ __forceinline__ void gbody(
    const __half* __restrict__ Ah, const __half* __restrict__ Al,
    const __half* __restrict__ Bh, const __half* __restrict__ Bl,
    float* __restrict__ Cf, __half* __restrict__ Ch,
    const float* __restrict__ bias, const float* __restrict__ rowsc,
    int M, int N, int K, int ldA, int ldB, float alpha,
    size_t sA, size_t sB, size_t sC, int zz_in)
{
    constexpr int NPA = ASPL ? 2 : 1;
    constexpr int NP  = NPA + (BSPL ? 2 : 1);
    constexpr int STG = NP * SLOT;

    extern __shared__ char sm[];
    const uint32_t sb = smem_u32(sm);

    const int tid  = threadIdx.x;
    const int lane = tid & 31;
    const int w    = tid >> 5;
    const int wm   = w & 1;
    const int wn   = w >> 1;
    const int g    = lane >> 2;
    const int t    = lane & 3;

    const size_t zz = zz_in;
    const __half* Ahb = Ah + zz * sA;
    const __half* Alb = ASPL ? Al + zz * sA : nullptr;
    const __half* Bhb = Bh + zz * sB;
    const __half* Blb = BSPL ? Bl + zz * sB : nullptr;
    const int bm = blockIdx.y * TM;
    const int bn = blockIdx.x * TN;

    // fragment address components
    const int a_r   = ((lane >> 3) & 1) * 8 + (lane & 7);
    const int a_c8  = (lane >> 4) * 8;
    const int b_r   = (lane >> 4) * 8 + (lane & 7);
    const int b_c8  = ((lane >> 3) & 1) * 8;
    const int at_r  = (lane >> 4) * 8 + (lane & 7);
    const int at_c8 = ((lane >> 3) & 1) * 8;
    const int bt_r  = ((lane >> 3) & 1) * 8 + (lane & 7);
    const int bt_c8 = (lane >> 4) * 8;

    float acc[4][4][4];
#pragma unroll
    for (int i = 0; i < 4; i++)
#pragma unroll
        for (int j = 0; j < 4; j++)
#pragma unroll
            for (int e = 0; e < 4; e++) acc[i][j][e] = 0.0f;

    const int NK = K / TKF;

    auto issue = [&](int kt, int p) {
        const uint32_t st = sb + p * STG;
        if (!TRANS) {
#pragma unroll
            for (int j = 0; j < 2; j++) {
                const int idx = tid * 2 + j;
                const int r = idx >> 2, c = idx & 3;
                const uint32_t so = (uint32_t)(r * PNT + c * 16);
                const size_t goA = (size_t)(bm + r) * ldA + kt * TKF + c * 8;
                const size_t goB = (size_t)(bn + r) * ldB + kt * TKF + c * 8;
                cp16(st + so, Ahb + goA);
                if (ASPL) cp16(st + SLOT + so, Alb + goA);
                cp16(st + NPA * SLOT + so, Bhb + goB);
                if (BSPL) cp16(st + (NPA + 1) * SLOT + so, Blb + goB);
            }
        } else {
#pragma unroll
            for (int j = 0; j < 2; j++) {
                const int idx = tid * 2 + j;
                const int r = idx >> 4, c = idx & 15;
                const uint32_t so = (uint32_t)(r * PTR + c * 16);
                const size_t goA = (size_t)(kt * TKF + r) * ldA + bm + c * 8;
                const size_t goB = (size_t)(kt * TKF + r) * ldB + bn + c * 8;
                cp16(st + so, Ahb + goA);
                if (ASPL) cp16(st + SLOT + so, Alb + goA);
                cp16(st + NPA * SLOT + so, Bhb + goB);
                if (BSPL) cp16(st + (NPA + 1) * SLOT + so, Blb + goB);
            }
        }
    };

    // prologue: fill STAGES-1 buffers, one commit group per tile
#pragma unroll
    for (int s = 0; s < STAGES - 1; s++) {
        if (s < NK) issue(s, s);
        cp_commit();
    }

    for (int kt = 0; kt < NK; kt++) {
        const int p = kt % STAGES;

        cp_wait<STAGES - 2>();   // tile kt resident
        __syncthreads();         // all warps done with tile kt-1's buffer

        const uint32_t sa_hi = sb + p * STG;
        const uint32_t sa_lo = sa_hi + SLOT;
        const uint32_t sb_hi = sa_hi + NPA * SLOT;
        const uint32_t sb_lo = sb_hi + SLOT;

#pragma unroll
        for (int ks = 0; ks < 2; ks++) {
            const int k0 = ks * 16;

            uint32_t bh[8], bl[8];
#pragma unroll
            for (int j = 0; j < 2; j++) {
                uint32_t addr;
                if (!TRANS) {
                    addr = (uint32_t)((wn * 32 + j * 16 + b_r) * PNT +
                                      (k0 + b_c8) * 2);
                    ldsm4(bh + 4 * j, sb_hi + addr);
                    if (BSPL) ldsm4(bl + 4 * j, sb_lo + addr);
                } else {
                    addr = (uint32_t)((k0 + bt_r) * PTR +
                                      (wn * 32 + j * 16 + bt_c8) * 2);
                    ldsm4t(bh + 4 * j, sb_hi + addr);
                    if (BSPL) ldsm4t(bl + 4 * j, sb_lo + addr);
                }
            }

            uint32_t ah[4][4], al[4][4];
#pragma unroll
            for (int mf = 0; mf < 4; mf++) {
                uint32_t addr;
                if (!TRANS) {
                    addr = (uint32_t)((wm * 64 + mf * 16 + a_r) * PNT +
                                      (k0 + a_c8) * 2);
                    ldsm4(ah[mf], sa_hi + addr);
                    if (ASPL) ldsm4(al[mf], sa_lo + addr);
                } else {
                    addr = (uint32_t)((k0 + at_r) * PTR +
                                      (wm * 64 + mf * 16 + at_c8) * 2);
                    ldsm4t(ah[mf], sa_hi + addr);
                    if (ASPL) ldsm4t(al[mf], sa_lo + addr);
                }
            }

#pragma unroll
            for (int mf = 0; mf < 4; mf++)
#pragma unroll
                for (int nf = 0; nf < 4; nf++) {
                    mma16816(acc[mf][nf], ah[mf], bh + 2 * nf);
                    if (ASPL) mma16816(acc[mf][nf], al[mf], bh + 2 * nf);
                    if (BSPL) mma16816(acc[mf][nf], ah[mf], bl + 2 * nf);
                }
        }

        // refill AFTER compute: writes slot (kt+STAGES-1)%STAGES = tile kt-1's
        // buffer, which every warp released at this iteration's __syncthreads.
        if (kt + STAGES - 1 < NK) issue(kt + STAGES - 1, (kt + STAGES - 1) % STAGES);
        cp_commit();             // keep group numbering aligned (may be empty)
    }

    // ---------------- epilogues ----------------
    if (EPI == 2) {
        __syncthreads();  // smem 'red' reuses pipeline buffers
        __half* Cb = Ch + zz * sC;
        const float* vr = g_vrow + zz * SLEN;
        float cs[8];
#pragma unroll
        for (int j = 0; j < 8; j++) cs[j] = 0.0f;

#pragma unroll
        for (int mf = 0; mf < 4; mf++) {
            const int row0 = bm + wm * 64 + mf * 16 + g;
            const int row1 = row0 + 8;
            const float v0 = vr[row0], v1 = vr[row1];
#pragma unroll
            for (int nf = 0; nf < 4; nf++) {
                const int col = bn + wn * 32 + nf * 8 + 2 * t;
                float e00 = __expf(alpha * acc[mf][nf][0] + v0);
                float e01 = __expf(alpha * acc[mf][nf][1] + v0);
                float e10 = __expf(alpha * acc[mf][nf][2] + v1);
                float e11 = __expf(alpha * acc[mf][nf][3] + v1);
                *(__half2*)(Cb + (size_t)row0 * N + col) =
                    __floats2half2_rn(e00, e01);
                *(__half2*)(Cb + (size_t)row1 * N + col) =
                    __floats2half2_rn(e10, e11);
                cs[nf * 2 + 0] += e00 + e10;
                cs[nf * 2 + 1] += e01 + e11;
            }
        }
        float* red = (float*)sm;  // 256 floats
#pragma unroll
        for (int j = 0; j < 8; j++) {
#pragma unroll
            for (int o = 4; o <= 16; o <<= 1)
                cs[j] += __shfl_xor_sync(0xFFFFFFFFu, cs[j], o);
        }
        if (lane < 4) {
#pragma unroll
            for (int nf = 0; nf < 4; nf++) {
                red[wm * 128 + wn * 32 + nf * 8 + 2 * t + 0] = cs[nf * 2 + 0];
                red[wm * 128 + wn * 32 + nf * 8 + 2 * t + 1] = cs[nf * 2 + 1];
            }
        }
        __syncthreads();
        if (tid < 128) {
            g_part[((zz * 16) + blockIdx.y) * QLEN + bn + tid] =
                red[tid] + red[128 + tid];
        }
    } else {
#pragma unroll
        for (int mf = 0; mf < 4; mf++) {
            const int row0 = bm + wm * 64 + mf * 16 + g;
            const int row1 = row0 + 8;
            float s0 = 1.0f, s1 = 1.0f;
            if (rowsc != nullptr) {
                s0 = rowsc[zz * M + row0];
                s1 = rowsc[zz * M + row1];
            }
#pragma unroll
            for (int nf = 0; nf < 4; nf++) {
                const int col = bn + wn * 32 + nf * 8 + 2 * t;
                float bx = 0.0f, by = 0.0f;
                if (bias != nullptr) { bx = bias[col]; by = bias[col + 1]; }
                float o0x = s0 * (alpha * acc[mf][nf][0]) + bx;
                float o0y = s0 * (alpha * acc[mf][nf][1]) + by;
                float o1x = s1 * (alpha * acc[mf][nf][2]) + bx;
                float o1y = s1 * (alpha * acc[mf][nf][3]) + by;
                if (EPI == 0) {
                    float* Cb = Cf + zz * sC;
                    *(float2*)(Cb + (size_t)row0 * N + col) = make_float2(o0x, o0y);
                    *(float2*)(Cb + (size_t)row1 * N + col) = make_float2(o1x, o1y);
                } else {
                    __half* Cb = Ch + zz * sC;
                    *(__half2*)(Cb + (size_t)row0 * N + col) =
                        __floats2half2_rn(o0x, o0y);
                    *(__half2*)(Cb + (size_t)row1 * N + col) =
                        __floats2half2_rn(o1x, o1y);
                }
            }
        }
    }
}

// ---------------- instantiations ----------------
// Mt with 4-way k-split: blockIdx.z picks the K chunk; f32 partials out.
extern "C" __global__ void __launch_bounds__(256)
k_mt4()
{
    gbody<true, true, true, 0, 2>(
        g_Wqh, g_Wql, g_Wkh, g_Wkl, g_MtP, nullptr, nullptr, nullptr,
        HID, HID, HID / 4, HID, HID, 32.0f,
        (size_t)(HID / 4) * HID,      // A k-chunk offset ([K,M] row-major)
        (size_t)(HID / 4) * HID,      // B k-chunk offset
        (size_t)HID * HID,            // partial-buffer stride
        blockIdx.z);
}

// reduce 4 Mt partials -> half
extern "C" __global__ void __launch_bounds__(256)
mt_red_k()
{
    const int i = blockIdx.x * 256 + threadIdx.x;   // float4 index, 262144 total
    const float4* p = (const float4*)g_MtP;
    const int n4 = (HID * HID) / 4;
    float4 s = p[i];
#pragma unroll
    for (int j = 1; j < 4; j++) {
        float4 t = p[i + j * n4];
        s.x += t.x; s.y += t.y; s.z += t.z; s.w += t.w;
    }
    __half2 h0 = __floats2half2_rn(s.x, s.y);
    __half2 h1 = __floats2half2_rn(s.z, s.w);
    ((uint2*)g_Mth)[i] = make_uint2(*(uint32_t*)&h0, *(uint32_t*)&h1);
}

// merged Vp + KM: blockIdx.z selects the problem
extern "C" __global__ void __launch_bounds__(256, 2)
k_proj2(const float* bv)
{
    if (blockIdx.z == 0)
        gbody<false, false, false, 1, 4>(
            g_Vh, nullptr, g_Wvh, nullptr, nullptr, g_Vph, bv, nullptr,
            BNUM * SLEN, HID, HID, HID, HID, 1.0f, 0, 0, 0, 0);
    else
        gbody<false, false, false, 1, 4>(
            g_Kh, nullptr, g_Mth, nullptr, nullptr, g_KMh, nullptr, nullptr,
            BNUM * SLEN, HID, HID, HID, HID, 0.03125f, 0, 0, 0, 0);
}

extern "C" __global__ void __launch_bounds__(256, 2)
k_sc(const __half* Ah, const __half* Bh, __half* Ch,
     int M, int N, int K, float alpha, size_t sA, size_t sB, size_t sC)
{ gbody<false, false, false, 2, 4>(Ah, nullptr, Bh, nullptr, nullptr, Ch,
                                   nullptr, nullptr, M, N, K, K, K, alpha,
                                   sA, sB, sC, blockIdx.z); }

// merged ctx GEMM (z<8) + attn normalization (z>=8)
extern "C" __global__ void __launch_bounds__(256, 2)
k_ctxn(float* __restrict__ ctx, float* __restrict__ attn)
{
    if (blockIdx.z < 8) {
        gbody<true, false, false, 0, 4>(
            g_Ph, nullptr, g_Vph, nullptr, ctx, nullptr, nullptr, g_inv,
            QLEN, HID, SLEN, QLEN, HID, 1.0f,
            (size_t)SLEN * QLEN, (size_t)SLEN * HID, (size_t)QLEN * HID,
            blockIdx.z);
    } else {
        // norm: attn[b,s,q] = Ph[b,s,q] * inv[b,q]
        const int cid = ((int)blockIdx.z - 8) * 128 + blockIdx.y * 8 + blockIdx.x;
        const uint2* ph4 = (const uint2*)g_Ph;
        float4* out = (float4*)attn;
        const int base = cid * 8192 + threadIdx.x;   // 1024 CTAs * 8192 f4
#pragma unroll 4
        for (int j = 0; j < 32; j++) {
            const int i = base + j * 256;
            uint2 u = ph4[i];
            const int e0 = i * 4;
            const int q  = e0 & (QLEN - 1);
            const int b  = e0 >> 22;
            float4 inv = *(const float4*)(g_inv + ((size_t)b << 11) + q);
            __half2 h0 = *(__half2*)&u.x;
            __half2 h1 = *(__half2*)&u.y;
            float2 f0 = __half22float2(h0), f1 = __half22float2(h1);
            float4 o;
            o.x = f0.x * inv.x; o.y = f0.y * inv.y;
            o.z = f1.x * inv.z; o.w = f1.y * inv.w;
            out[i] = o;
        }
    }
}

// ---------------- f32 -> half conversions ----------------
// merged weight conversion: z=0 Wq(split), z=1 Wk(split), z=2 Wv(hi)
extern "C" __global__ void __launch_bounds__(256)
cvtw_k(const float4* __restrict__ Wq, const float4* __restrict__ Wk,
       const float4* __restrict__ Wv)
{
    const int n4 = (HID * HID) / 4;
    const int z = blockIdx.z;
    const float4* in = (z == 0) ? Wq : (z == 1) ? Wk : Wv;
    uint2* hi = (z == 0) ? (uint2*)g_Wqh : (z == 1) ? (uint2*)g_Wkh
                                                    : (uint2*)g_Wvh;
    uint2* lo = (z == 0) ? (uint2*)g_Wql : (uint2*)g_Wkl;
    for (int i = blockIdx.x * 256 + threadIdx.x; i < n4; i += gridDim.x * 256) {
        float4 v = in[i];
        __half2 h0 = __floats2half2_rn(v.x, v.y);
        __half2 h1 = __floats2half2_rn(v.z, v.w);
        hi[i] = make_uint2(*(uint32_t*)&h0, *(uint32_t*)&h1);
        if (z < 2) {
            float2 f0 = __half22float2(h0), f1 = __half22float2(h1);
            __half2 l0 = __floats2half2_rn(v.x - f0.x, v.y - f0.y);
            __half2 l1 = __floats2half2_rn(v.z - f1.x, v.w - f1.y);
            lo[i] = make_uint2(*(uint32_t*)&l0, *(uint32_t*)&l1);
        }
    }
}
// merged q/k/v hi-conversion: blockIdx.z picks the tensor
extern "C" __global__ void __launch_bounds__(256)
cvt3_k(const float4* __restrict__ q, const float4* __restrict__ k,
       const float4* __restrict__ v, int n4)
{
    const float4* in = (blockIdx.z == 0) ? q : (blockIdx.z == 1) ? k : v;
    uint2* out = (blockIdx.z == 0) ? (uint2*)g_Qh
               : (blockIdx.z == 1) ? (uint2*)g_Kh : (uint2*)g_Vh;
    for (int i = blockIdx.x * 256 + threadIdx.x; i < n4; i += gridDim.x * 256) {
        float4 x = in[i];
        __half2 h0 = __floats2half2_rn(x.x, x.y);
        __half2 h1 = __floats2half2_rn(x.z, x.w);
        out[i] = make_uint2(*(uint32_t*)&h0, *(uint32_t*)&h1);
    }
}

// ---------------- bias rank-1 correction (general-bq path) ----------------
__global__ void __launch_bounds__(256)
veca_k(const float* __restrict__ Wk, const float* __restrict__ bq)
{
    int any = 0;
    for (int i = threadIdx.x; i < HID; i += 256) any |= (bq[i] != 0.0f);
    const int r = __syncthreads_or(any);
    if (threadIdx.x == 0 && blockIdx.x == 0) g_flag = r ? 1 : 0;

    const int i = blockIdx.x * 256 + threadIdx.x;
    float s = 0.0f;
    if (r) {
        for (int o = 0; o < HID; o++) s += Wk[(size_t)o * HID + i] * bq[o];
    }
    g_vec[i] = s;
}
__global__ void __launch_bounds__(256)
vrow_k(const float* __restrict__ keys)
{
    const int r = blockIdx.x * 256 + threadIdx.x;
    float s = 0.0f;
    if (g_flag) {
        const float* kr = keys + (size_t)r * HID;
        for (int i = 0; i < HID; i++) s += kr[i] * g_vec[i];
    }
    g_vrow[r] = s;
}

// ---------------- per-q inverse sums ----------------
__global__ void __launch_bounds__(256) inv_k()
{
    const int i = blockIdx.x * 256 + threadIdx.x;   // b*QLEN + q
    const int b = i >> 11, q = i & (QLEN - 1);
    float tot = 0.0f;
#pragma unroll
    for (int j = 0; j < 16; j++)
        tot += g_part[((size_t)b * 16 + j) * QLEN + q];
    g_inv[i] = 1.0f / tot;
}

// ---------------- launcher (R11/R15 topology, best measured: 827.5 us) ----
extern "C" void kernel_launch(void* const* d_in, const int* in_sizes, int n_in,
                              void* d_out, int out_size)
{
    const float* queries = (const float*)d_in[0];
    const float* keys    = (const float*)d_in[1];
    const float* values  = (const float*)d_in[2];
    const float* Wq      = (const float*)d_in[3];
    const float* bq      = (const float*)d_in[4];
    const float* Wk      = (const float*)d_in[5];
    // d_in[6] = bk: enters scores only via per-q constants -> cancels in softmax
    const float* Wv      = (const float*)d_in[7];
    const float* bv      = (const float*)d_in[8];

    float* ctx  = (float*)d_out;                                // [B,Q,H]
    float* attn = (float*)d_out + (size_t)BNUM * QLEN * HID;    // [B,S,Q]

    __half *qh, *kmh, *ph;
    cudaGetSymbolAddress((void**)&qh, g_Qh);
    cudaGetSymbolAddress((void**)&kmh, g_KMh);
    cudaGetSymbolAddress((void**)&ph, g_Ph);

    static cudaStream_t s1 = nullptr;
    static cudaEvent_t  evFork = nullptr, evJoin = nullptr;
    static bool init_done = false;
    if (!init_done) {
        cudaStreamCreateWithFlags(&s1, cudaStreamNonBlocking);
        cudaEventCreateWithFlags(&evFork, cudaEventDisableTiming);
        cudaEventCreateWithFlags(&evJoin, cudaEventDisableTiming);
        cudaFuncSetAttribute(k_mt4,   cudaFuncAttributeMaxDynamicSharedMemorySize, 2 * 4 * SLOT);
        cudaFuncSetAttribute(k_proj2, cudaFuncAttributeMaxDynamicSharedMemorySize, 4 * 2 * SLOT);
        cudaFuncSetAttribute(k_sc,    cudaFuncAttributeMaxDynamicSharedMemorySize, 4 * 2 * SLOT);
        cudaFuncSetAttribute(k_ctxn,  cudaFuncAttributeMaxDynamicSharedMemorySize, 4 * 2 * SLOT);
        init_done = true;
    }

    const int nBig4 = (BNUM * SLEN * HID) / 4;

    // ---- fork: weight-conversion + Mt chain on side stream s1 ----
    cudaEventRecord(evFork, 0);
    cudaStreamWaitEvent(s1, evFork, 0);
    cvtw_k<<<dim3(256, 1, 3), 256, 0, s1>>>((const float4*)Wq,
                                            (const float4*)Wk,
                                            (const float4*)Wv);
    k_mt4<<<dim3(8, 8, 4), 256, 2 * 4 * SLOT, s1>>>();
    mt_red_k<<<(HID * HID / 4) / 256, 256, 0, s1>>>();
    cudaEventRecord(evJoin, s1);

    // ---- main stream: bias chain + activation conversions (overlaps s1) ----
    veca_k<<<HID / 256, 256>>>(Wk, bq);
    vrow_k<<<(BNUM * SLEN) / 256, 256>>>(keys);
    cvt3_k<<<dim3(2048, 1, 3), 256>>>((const float4*)queries,
                                      (const float4*)keys,
                                      (const float4*)values, nBig4);

    // ---- join: everything below needs both tracks ----
    cudaStreamWaitEvent(0, evJoin, 0);

    // merged Vp (z=0) and KM (z=1)
    k_proj2<<<dim3(HID / TN, (BNUM * SLEN) / TM, 2), 256, 4 * 2 * SLOT>>>(bv);

    // Ph[b,s,q] = f16(exp((1/32)*KM.q + vrow)) + col-sum partials
    k_sc<<<dim3(QLEN / TN, SLEN / TM, BNUM), 256, 4 * 2 * SLOT>>>(
        kmh, qh, ph, SLEN, QLEN, HID, 0.03125f,
        (size_t)SLEN * HID, (size_t)QLEN * HID, (size_t)SLEN * QLEN);

    // per-q inverse sums
    inv_k<<<(BNUM * QLEN) / 256, 256>>>();

    // merged: ctx GEMM (z<8, row-scaled by inv) + attn normalization (z>=8)
    k_ctxn<<<dim3(HID / TN, QLEN / TM, 16), 256, 4 * 2 * SLOT>>>(ctx, attn);
}

// round 17
// speedup vs baseline: 1.0951x; 1.0154x over previous
#include <cuda_runtime.h>
#include <cuda_fp16.h>
#include <cstdint>

#define HID   1024
#define BNUM  8
#define SLEN  2048
#define QLEN  2048

// ---------------- scratch: fp16 operand planes (allocation-free) -----------
__device__ __half g_Qh[(size_t)BNUM * QLEN * HID];
__device__ __half g_Kh[(size_t)BNUM * SLEN * HID];
__device__ __half g_Vh[(size_t)BNUM * SLEN * HID];
__device__ __half g_Wqh[(size_t)HID * HID];
__device__ __half g_Wql[(size_t)HID * HID];
__device__ __half g_Wkh[(size_t)HID * HID];
__device__ __half g_Wkl[(size_t)HID * HID];
__device__ __half g_Wvh[(size_t)HID * HID];
__device__ __half g_Mth[(size_t)HID * HID];          // 32 * Wq^T Wk (hi)
__device__ float  g_MtP[(size_t)4 * HID * HID];      // Mt k-split partials
__device__ __half g_KMh[(size_t)BNUM * SLEN * HID];  // keys*M (hi)
__device__ __half g_Vph[(size_t)BNUM * SLEN * HID];  // V proj (hi)
__device__ __half g_Ph [(size_t)BNUM * SLEN * QLEN]; // exp(scores) f16 (unnorm)
__device__ float  g_part[(size_t)BNUM * 16 * QLEN];  // col-sum partials
__device__ float  g_inv [(size_t)BNUM * QLEN];       // 1 / col sums
__device__ float  g_vrow[(size_t)BNUM * SLEN];       // keys * (Wk^T bq)
__device__ float  g_vec[HID];
__device__ int    g_flag;

// ---------------- geometry ----------------
#define TM   128
#define TN   128
#define TKF  32
#define SLOT 10240         // one plane-tile slot (max of NT 10240 / TN 8704)
#define PNT  80            // NT tile row pitch (64B data + 16B pad)
#define PTR  272           // TRANS tile row pitch (256B data + 16B pad)

// ---------------- PTX helpers ----------------
__device__ __forceinline__ uint32_t smem_u32(const void* p) {
    uint32_t a;
    asm("{ .reg .u64 t; cvta.to.shared.u64 t, %1; cvt.u32.u64 %0, t; }"
        : "=r"(a) : "l"(p));
    return a;
}
__device__ __forceinline__ void cp16(uint32_t s, const void* g) {
    asm volatile("cp.async.cg.shared.global [%0], [%1], 16;"
                 :: "r"(s), "l"(g));
}
__device__ __forceinline__ void cp_commit() {
    asm volatile("cp.async.commit_group;" ::: "memory");
}
template <int N_>
__device__ __forceinline__ void cp_wait() {
    asm volatile("cp.async.wait_group %0;" :: "n"(N_) : "memory");
}
__device__ __forceinline__ void ldsm4(uint32_t* r, uint32_t addr) {
    asm volatile("ldmatrix.sync.aligned.m8n8.x4.shared.b16 {%0,%1,%2,%3}, [%4];"
                 : "=r"(r[0]), "=r"(r[1]), "=r"(r[2]), "=r"(r[3]) : "r"(addr));
}
__device__ __forceinline__ void ldsm4t(uint32_t* r, uint32_t addr) {
    asm volatile("ldmatrix.sync.aligned.m8n8.x4.trans.shared.b16 {%0,%1,%2,%3}, [%4];"
                 : "=r"(r[0]), "=r"(r[1]), "=r"(r[2]), "=r"(r[3]) : "r"(addr));
}
__device__ __forceinline__ void mma16816(float* c, const uint32_t* a,
                                         const uint32_t* b) {
    asm volatile(
        "mma.sync.aligned.m16n8k16.row.col.f32.f16.f16.f32 "
        "{%0,%1,%2,%3}, {%4,%5,%6,%7}, {%8,%9}, {%0,%1,%2,%3};"
        : "+f"(c[0]), "+f"(c[1]), "+f"(c[2]), "+f"(c[3])
        : "r"(a[0]), "r"(a[1]), "r"(a[2]), "r"(a[3]), "r"(b[0]), "r"(b[1]));
}

// ---------------------------------------------------------------------------
// Unified fp16 tensor-core GEMM over pre-converted half planes.
// NT (TRANS=0): C[m,n] = alpha*sum_k A[m,k]*B[n,k], A:[M,K], B:[N,K]
// TN (TRANS=1): C[m,n] = alpha*sum_k A[k,m]*B[k,n], A:[K,M], B:[K,N]
// ASPL/BSPL: lo-residual planes (extra MMA each).
// EPI: 0 = f32 out (+bias) [optionally * rowsc[row]];
//      1 = half out (+bias);
//      2 = exp epilogue: writes f16 exp to Ch, col-sum partials to g_part.
// STAGES: cp.async pipeline depth (one __syncthreads per k-iter).
// Mainloop scheduling (asm volatile preserves order):
//  - refill issue AFTER compute (keeps LDGSTS off the ldsm->MMA path)
//  - A-fragment ldsm for mf+1 issued BEFORE mf's MMA group (latency hidden
//    behind a full 4-MMA group of tensor work).
// ---------------------------------------------------------------------------
template <bool TRANS, bool ASPL, bool BSPL, int EPI, int STAGES>
__device__ __forceinline__ void gbody(
    const __half* __restrict__ Ah, const __half* __restrict__ Al,
    const __half* __restrict__ Bh, const __half* __restrict__ Bl,
    float* __restrict__ Cf, __half* __restrict__ Ch,
    const float* __restrict__ bias, const float* __restrict__ rowsc,
    int M, int N, int K, int ldA, int ldB, float alpha,
    size_t sA, size_t sB, size_t sC, int zz_in)
{
    constexpr int NPA = ASPL ? 2 : 1;
    constexpr int NP  = NPA + (BSPL ? 2 : 1);
    constexpr int STG = NP * SLOT;

    extern __shared__ char sm[];
    const uint32_t sb = smem_u32(sm);

    const int tid  = threadIdx.x;
    const int lane = tid & 31;
    const int w    = tid >> 5;
    const int wm   = w & 1;
    const int wn   = w >> 1;
    const int g    = lane >> 2;
    const int t    = lane & 3;

    const size_t zz = zz_in;
    const __half* Ahb = Ah + zz * sA;
    const __half* Alb = ASPL ? Al + zz * sA : nullptr;
    const __half* Bhb = Bh + zz * sB;
    const __half* Blb = BSPL ? Bl + zz * sB : nullptr;
    const int bm = blockIdx.y * TM;
    const int bn = blockIdx.x * TN;

    // fragment address components
    const int a_r   = ((lane >> 3) & 1) * 8 + (lane & 7);
    const int a_c8  = (lane >> 4) * 8;
    const int b_r   = (lane >> 4) * 8 + (lane & 7);
    const int b_c8  = ((lane >> 3) & 1) * 8;
    const int at_r  = (lane >> 4) * 8 + (lane & 7);
    const int at_c8 = ((lane >> 3) & 1) * 8;
    const int bt_r  = ((lane >> 3) & 1) * 8 + (lane & 7);
    const int bt_c8 = (lane >> 4) * 8;

    float acc[4][4][4];
#pragma unroll
    for (int i = 0; i < 4; i++)
#pragma unroll
        for (int j = 0; j < 4; j++)
#pragma unroll
            for (int e = 0; e < 4; e++) acc[i][j][e] = 0.0f;

    const int NK = K / TKF;

    auto issue = [&](int kt, int p) {
        const uint32_t st = sb + p * STG;
        if (!TRANS) {
#pragma unroll
            for (int j = 0; j < 2; j++) {
                const int idx = tid * 2 + j;
                const int r = idx >> 2, c = idx & 3;
                const uint32_t so = (uint32_t)(r * PNT + c * 16);
                const size_t goA = (size_t)(bm + r) * ldA + kt * TKF + c * 8;
                const size_t goB = (size_t)(bn + r) * ldB + kt * TKF + c * 8;
                cp16(st + so, Ahb + goA);
                if (ASPL) cp16(st + SLOT + so, Alb + goA);
                cp16(st + NPA * SLOT + so, Bhb + goB);
                if (BSPL) cp16(st + (NPA + 1) * SLOT + so, Blb + goB);
            }
        } else {
#pragma unroll
            for (int j = 0; j < 2; j++) {
                const int idx = tid * 2 + j;
                const int r = idx >> 4, c = idx & 15;
                const uint32_t so = (uint32_t)(r * PTR + c * 16);
                const size_t goA = (size_t)(kt * TKF + r) * ldA + bm + c * 8;
                const size_t goB = (size_t)(kt * TKF + r) * ldB + bn + c * 8;
                cp16(st + so, Ahb + goA);
                if (ASPL) cp16(st + SLOT + so, Alb + goA);
                cp16(st + NPA * SLOT + so, Bhb + goB);
                if (BSPL) cp16(st + (NPA + 1) * SLOT + so, Blb + goB);
            }
        }
    };

    // per-fragment A ldsm (hi + optional lo)
    auto ld_afrag = [&](uint32_t sa_hi, uint32_t sa_lo, int k0, int mf,
                        uint32_t* ah, uint32_t* al) {
        uint32_t addr;
        if (!TRANS) {
            addr = (uint32_t)((wm * 64 + mf * 16 + a_r) * PNT +
                              (k0 + a_c8) * 2);
            ldsm4(ah, sa_hi + addr);
            if (ASPL) ldsm4(al, sa_lo + addr);
        } else {
            addr = (uint32_t)((k0 + at_r) * PTR +
                              (wm * 64 + mf * 16 + at_c8) * 2);
            ldsm4t(ah, sa_hi + addr);
            if (ASPL) ldsm4t(al, sa_lo + addr);
        }
    };

    // prologue: fill STAGES-1 buffers, one commit group per tile
#pragma unroll
    for (int s = 0; s < STAGES - 1; s++) {
        if (s < NK) issue(s, s);
        cp_commit();
    }

    for (int kt = 0; kt < NK; kt++) {
        const int p = kt % STAGES;

        cp_wait<STAGES - 2>();   // tile kt resident
        __syncthreads();         // all warps done with tile kt-1's buffer

        const uint32_t sa_hi = sb + p * STG;
        const uint32_t sa_lo = sa_hi + SLOT;
        const uint32_t sb_hi = sa_hi + NPA * SLOT;
        const uint32_t sb_lo = sb_hi + SLOT;

#pragma unroll
        for (int ks = 0; ks < 2; ks++) {
            const int k0 = ks * 16;

            // B fragments first
            uint32_t bh[8], bl[8];
#pragma unroll
            for (int j = 0; j < 2; j++) {
                uint32_t addr;
                if (!TRANS) {
                    addr = (uint32_t)((wn * 32 + j * 16 + b_r) * PNT +
                                      (k0 + b_c8) * 2);
                    ldsm4(bh + 4 * j, sb_hi + addr);
                    if (BSPL) ldsm4(bl + 4 * j, sb_lo + addr);
                } else {
                    addr = (uint32_t)((k0 + bt_r) * PTR +
                                      (wn * 32 + j * 16 + bt_c8) * 2);
                    ldsm4t(bh + 4 * j, sb_hi + addr);
                    if (BSPL) ldsm4t(bl + 4 * j, sb_lo + addr);
                }
            }

            // software-pipelined A fragments: ldsm(mf+1) issued before mma(mf)
            uint32_t ah[4][4], al[4][4];
            ld_afrag(sa_hi, sa_lo, k0, 0, ah[0], al[0]);
#pragma unroll
            for (int mf = 0; mf < 4; mf++) {
                if (mf + 1 < 4)
                    ld_afrag(sa_hi, sa_lo, k0, mf + 1, ah[mf + 1], al[mf + 1]);
#pragma unroll
                for (int nf = 0; nf < 4; nf++) {
                    mma16816(acc[mf][nf], ah[mf], bh + 2 * nf);
                    if (ASPL) mma16816(acc[mf][nf], al[mf], bh + 2 * nf);
                    if (BSPL) mma16816(acc[mf][nf], ah[mf], bl + 2 * nf);
                }
            }
        }

        // refill AFTER compute: writes slot (kt+STAGES-1)%STAGES = tile kt-1's
        // buffer, which every warp released at this iteration's __syncthreads.
        if (kt + STAGES - 1 < NK) issue(kt + STAGES - 1, (kt + STAGES - 1) % STAGES);
        cp_commit();             // keep group numbering aligned (may be empty)
    }

    // ---------------- epilogues ----------------
    if (EPI == 2) {
        __syncthreads();  // smem 'red' reuses pipeline buffers
        __half* Cb = Ch + zz * sC;
        const float* vr = g_vrow + zz * SLEN;
        float cs[8];
#pragma unroll
        for (int j = 0; j < 8; j++) cs[j] = 0.0f;

#pragma unroll
        for (int mf = 0; mf < 4; mf++) {
            const int row0 = bm + wm * 64 + mf * 16 + g;
            const int row1 = row0 + 8;
            const float v0 = vr[row0], v1 = vr[row1];
#pragma unroll
            for (int nf = 0; nf < 4; nf++) {
                const int col = bn + wn * 32 + nf * 8 + 2 * t;
                float e00 = __expf(alpha * acc[mf][nf][0] + v0);
                float e01 = __expf(alpha * acc[mf][nf][1] + v0);
                float e10 = __expf(alpha * acc[mf][nf][2] + v1);
                float e11 = __expf(alpha * acc[mf][nf][3] + v1);
                *(__half2*)(Cb + (size_t)row0 * N + col) =
                    __floats2half2_rn(e00, e01);
                *(__half2*)(Cb + (size_t)row1 * N + col) =
                    __floats2half2_rn(e10, e11);
                cs[nf * 2 + 0] += e00 + e10;
                cs[nf * 2 + 1] += e01 + e11;
            }
        }
        float* red = (float*)sm;  // 256 floats
#pragma unroll
        for (int j = 0; j < 8; j++) {
#pragma unroll
            for (int o = 4; o <= 16; o <<= 1)
                cs[j] += __shfl_xor_sync(0xFFFFFFFFu, cs[j], o);
        }
        if (lane < 4) {
#pragma unroll
            for (int nf = 0; nf < 4; nf++) {
                red[wm * 128 + wn * 32 + nf * 8 + 2 * t + 0] = cs[nf * 2 + 0];
                red[wm * 128 + wn * 32 + nf * 8 + 2 * t + 1] = cs[nf * 2 + 1];
            }
        }
        __syncthreads();
        if (tid < 128) {
            g_part[((zz * 16) + blockIdx.y) * QLEN + bn + tid] =
                red[tid] + red[128 + tid];
        }
    } else {
#pragma unroll
        for (int mf = 0; mf < 4; mf++) {
            const int row0 = bm + wm * 64 + mf * 16 + g;
            const int row1 = row0 + 8;
            float s0 = 1.0f, s1 = 1.0f;
            if (rowsc != nullptr) {
                s0 = rowsc[zz * M + row0];
                s1 = rowsc[zz * M + row1];
            }
#pragma unroll
            for (int nf = 0; nf < 4; nf++) {
                const int col = bn + wn * 32 + nf * 8 + 2 * t;
                float bx = 0.0f, by = 0.0f;
                if (bias != nullptr) { bx = bias[col]; by = bias[col + 1]; }
                float o0x = s0 * (alpha * acc[mf][nf][0]) + bx;
                float o0y = s0 * (alpha * acc[mf][nf][1]) + by;
                float o1x = s1 * (alpha * acc[mf][nf][2]) + bx;
                float o1y = s1 * (alpha * acc[mf][nf][3]) + by;
                if (EPI == 0) {
                    float* Cb = Cf + zz * sC;
                    *(float2*)(Cb + (size_t)row0 * N + col) = make_float2(o0x, o0y);
                    *(float2*)(Cb + (size_t)row1 * N + col) = make_float2(o1x, o1y);
                } else {
                    __half* Cb = Ch + zz * sC;
                    *(__half2*)(Cb + (size_t)row0 * N + col) =
                        __floats2half2_rn(o0x, o0y);
                    *(__half2*)(Cb + (size_t)row1 * N + col) =
                        __floats2half2_rn(o1x, o1y);
                }
            }
        }
    }
}

// ---------------- instantiations ----------------
// Mt with 4-way k-split: blockIdx.z picks the K chunk; f32 partials out.
extern "C" __global__ void __launch_bounds__(256)
k_mt4()
{
    gbody<true, true, true, 0, 2>(
        g_Wqh, g_Wql, g_Wkh, g_Wkl, g_MtP, nullptr, nullptr, nullptr,
        HID, HID, HID / 4, HID, HID, 32.0f,
        (size_t)(HID / 4) * HID,      // A k-chunk offset ([K,M] row-major)
        (size_t)(HID / 4) * HID,      // B k-chunk offset
        (size_t)HID * HID,            // partial-buffer stride
        blockIdx.z);
}

// reduce 4 Mt partials -> half
extern "C" __global__ void __launch_bounds__(256)
mt_red_k()
{
    const int i = blockIdx.x * 256 + threadIdx.x;   // float4 index, 262144 total
    const float4* p = (const float4*)g_MtP;
    const int n4 = (HID * HID) / 4;
    float4 s = p[i];
#pragma unroll
    for (int j = 1; j < 4; j++) {
        float4 t = p[i + j * n4];
        s.x += t.x; s.y += t.y; s.z += t.z; s.w += t.w;
    }
    __half2 h0 = __floats2half2_rn(s.x, s.y);
    __half2 h1 = __floats2half2_rn(s.z, s.w);
    ((uint2*)g_Mth)[i] = make_uint2(*(uint32_t*)&h0, *(uint32_t*)&h1);
}

// merged Vp + KM: blockIdx.z selects the problem
extern "C" __global__ void __launch_bounds__(256, 2)
k_proj2(const float* bv)
{
    if (blockIdx.z == 0)
        gbody<false, false, false, 1, 4>(
            g_Vh, nullptr, g_Wvh, nullptr, nullptr, g_Vph, bv, nullptr,
            BNUM * SLEN, HID, HID, HID, HID, 1.0f, 0, 0, 0, 0);
    else
        gbody<false, false, false, 1, 4>(
            g_Kh, nullptr, g_Mth, nullptr, nullptr, g_KMh, nullptr, nullptr,
            BNUM * SLEN, HID, HID, HID, HID, 0.03125f, 0, 0, 0, 0);
}

extern "C" __global__ void __launch_bounds__(256, 2)
k_sc(const __half* Ah, const __half* Bh, __half* Ch,
     int M, int N, int K, float alpha, size_t sA, size_t sB, size_t sC)
{ gbody<false, false, false, 2, 4>(Ah, nullptr, Bh, nullptr, nullptr, Ch,
                                   nullptr, nullptr, M, N, K, K, K, alpha,
                                   sA, sB, sC, blockIdx.z); }

// merged ctx GEMM (z<8) + attn normalization (z>=8)
extern "C" __global__ void __launch_bounds__(256, 2)
k_ctxn(float* __restrict__ ctx, float* __restrict__ attn)
{
    if (blockIdx.z < 8) {
        gbody<true, false, false, 0, 4>(
            g_Ph, nullptr, g_Vph, nullptr, ctx, nullptr, nullptr, g_inv,
            QLEN, HID, SLEN, QLEN, HID, 1.0f,
            (size_t)SLEN * QLEN, (size_t)SLEN * HID, (size_t)QLEN * HID,
            blockIdx.z);
    } else {
        // norm: attn[b,s,q] = Ph[b,s,q] * inv[b,q]
        const int cid = ((int)blockIdx.z - 8) * 128 + blockIdx.y * 8 + blockIdx.x;
        const uint2* ph4 = (const uint2*)g_Ph;
        float4* out = (float4*)attn;
        const int base = cid * 8192 + threadIdx.x;   // 1024 CTAs * 8192 f4
#pragma unroll 4
        for (int j = 0; j < 32; j++) {
            const int i = base + j * 256;
            uint2 u = ph4[i];
            const int e0 = i * 4;
            const int q  = e0 & (QLEN - 1);
            const int b  = e0 >> 22;
            float4 inv = *(const float4*)(g_inv + ((size_t)b << 11) + q);
            __half2 h0 = *(__half2*)&u.x;
            __half2 h1 = *(__half2*)&u.y;
            float2 f0 = __half22float2(h0), f1 = __half22float2(h1);
            float4 o;
            o.x = f0.x * inv.x; o.y = f0.y * inv.y;
            o.z = f1.x * inv.z; o.w = f1.y * inv.w;
            out[i] = o;
        }
    }
}

// ---------------- f32 -> half conversions ----------------
// merged weight conversion: z=0 Wq(split), z=1 Wk(split), z=2 Wv(hi)
extern "C" __global__ void __launch_bounds__(256)
cvtw_k(const float4* __restrict__ Wq, const float4* __restrict__ Wk,
       const float4* __restrict__ Wv)
{
    const int n4 = (HID * HID) / 4;
    const int z = blockIdx.z;
    const float4* in = (z == 0) ? Wq : (z == 1) ? Wk : Wv;
    uint2* hi = (z == 0) ? (uint2*)g_Wqh : (z == 1) ? (uint2*)g_Wkh
                                                    : (uint2*)g_Wvh;
    uint2* lo = (z == 0) ? (uint2*)g_Wql : (uint2*)g_Wkl;
    for (int i = blockIdx.x * 256 + threadIdx.x; i < n4; i += gridDim.x * 256) {
        float4 v = in[i];
        __half2 h0 = __floats2half2_rn(v.x, v.y);
        __half2 h1 = __floats2half2_rn(v.z, v.w);
        hi[i] = make_uint2(*(uint32_t*)&h0, *(uint32_t*)&h1);
        if (z < 2) {
            float2 f0 = __half22float2(h0), f1 = __half22float2(h1);
            __half2 l0 = __floats2half2_rn(v.x - f0.x, v.y - f0.y);
            __half2 l1 = __floats2half2_rn(v.z - f1.x, v.w - f1.y);
            lo[i] = make_uint2(*(uint32_t*)&l0, *(uint32_t*)&l1);
        }
    }
}
// merged q/k/v hi-conversion: blockIdx.z picks the tensor
extern "C" __global__ void __launch_bounds__(256)
cvt3_k(const float4* __restrict__ q, const float4* __restrict__ k,
       const float4* __restrict__ v, int n4)
{
    const float4* in = (blockIdx.z == 0) ? q : (blockIdx.z == 1) ? k : v;
    uint2* out = (blockIdx.z == 0) ? (uint2*)g_Qh
               : (blockIdx.z == 1) ? (uint2*)g_Kh : (uint2*)g_Vh;
    for (int i = blockIdx.x * 256 + threadIdx.x; i < n4; i += gridDim.x * 256) {
        float4 x = in[i];
        __half2 h0 = __floats2half2_rn(x.x, x.y);
        __half2 h1 = __floats2half2_rn(x.z, x.w);
        out[i] = make_uint2(*(uint32_t*)&h0, *(uint32_t*)&h1);
    }
}

// ---------------- bias rank-1 correction (general-bq path) ----------------
__global__ void __launch_bounds__(256)
veca_k(const float* __restrict__ Wk, const float* __restrict__ bq)
{
    int any = 0;
    for (int i = threadIdx.x; i < HID; i += 256) any |= (bq[i] != 0.0f);
    const int r = __syncthreads_or(any);
    if (threadIdx.x == 0 && blockIdx.x == 0) g_flag = r ? 1 : 0;

    const int i = blockIdx.x * 256 + threadIdx.x;
    float s = 0.0f;
    if (r) {
        for (int o = 0; o < HID; o++) s += Wk[(size_t)o * HID + i] * bq[o];
    }
    g_vec[i] = s;
}
__global__ void __launch_bounds__(256)
vrow_k(const float* __restrict__ keys)
{
    const int r = blockIdx.x * 256 + threadIdx.x;
    float s = 0.0f;
    if (g_flag) {
        const float* kr = keys + (size_t)r * HID;
        for (int i = 0; i < HID; i++) s += kr[i] * g_vec[i];
    }
    g_vrow[r] = s;
}

// ---------------- per-q inverse sums ----------------
__global__ void __launch_bounds__(256) inv_k()
{
    const int i = blockIdx.x * 256 + threadIdx.x;   // b*QLEN + q
    const int b = i >> 11, q = i & (QLEN - 1);
    float tot = 0.0f;
#pragma unroll
    for (int j = 0; j < 16; j++)
        tot += g_part[((size_t)b * 16 + j) * QLEN + q];
    g_inv[i] = 1.0f / tot;
}

// ---------------- launcher (best measured topology: 783.7 us) -------------
extern "C" void kernel_launch(void* const* d_in, const int* in_sizes, int n_in,
                              void* d_out, int out_size)
{
    const float* queries = (const float*)d_in[0];
    const float* keys    = (const float*)d_in[1];
    const float* values  = (const float*)d_in[2];
    const float* Wq      = (const float*)d_in[3];
    const float* bq      = (const float*)d_in[4];
    const float* Wk      = (const float*)d_in[5];
    // d_in[6] = bk: enters scores only via per-q constants -> cancels in softmax
    const float* Wv      = (const float*)d_in[7];
    const float* bv      = (const float*)d_in[8];

    float* ctx  = (float*)d_out;                                // [B,Q,H]
    float* attn = (float*)d_out + (size_t)BNUM * QLEN * HID;    // [B,S,Q]

    __half *qh, *kmh, *ph;
    cudaGetSymbolAddress((void**)&qh, g_Qh);
    cudaGetSymbolAddress((void**)&kmh, g_KMh);
    cudaGetSymbolAddress((void**)&ph, g_Ph);

    static cudaStream_t s1 = nullptr;
    static cudaEvent_t  evFork = nullptr, evJoin = nullptr;
    static bool init_done = false;
    if (!init_done) {
        cudaStreamCreateWithFlags(&s1, cudaStreamNonBlocking);
        cudaEventCreateWithFlags(&evFork, cudaEventDisableTiming);
        cudaEventCreateWithFlags(&evJoin, cudaEventDisableTiming);
        cudaFuncSetAttribute(k_mt4,   cudaFuncAttributeMaxDynamicSharedMemorySize, 2 * 4 * SLOT);
        cudaFuncSetAttribute(k_proj2, cudaFuncAttributeMaxDynamicSharedMemorySize, 4 * 2 * SLOT);
        cudaFuncSetAttribute(k_sc,    cudaFuncAttributeMaxDynamicSharedMemorySize, 4 * 2 * SLOT);
        cudaFuncSetAttribute(k_ctxn,  cudaFuncAttributeMaxDynamicSharedMemorySize, 4 * 2 * SLOT);
        init_done = true;
    }

    const int nBig4 = (BNUM * SLEN * HID) / 4;

    // ---- fork: weight-conversion + Mt chain on side stream s1 ----
    cudaEventRecord(evFork, 0);
    cudaStreamWaitEvent(s1, evFork, 0);
    cvtw_k<<<dim3(256, 1, 3), 256, 0, s1>>>((const float4*)Wq,
                                            (const float4*)Wk,
                                            (const float4*)Wv);
    k_mt4<<<dim3(8, 8, 4), 256, 2 * 4 * SLOT, s1>>>();
    mt_red_k<<<(HID * HID / 4) / 256, 256, 0, s1>>>();
    cudaEventRecord(evJoin, s1);

    // ---- main stream: bias chain + activation conversions (overlaps s1) ----
    veca_k<<<HID / 256, 256>>>(Wk, bq);
    vrow_k<<<(BNUM * SLEN) / 256, 256>>>(keys);
    cvt3_k<<<dim3(2048, 1, 3), 256>>>((const float4*)queries,
                                      (const float4*)keys,
                                      (const float4*)values, nBig4);

    // ---- join: everything below needs both tracks ----
    cudaStreamWaitEvent(0, evJoin, 0);

    // merged Vp (z=0) and KM (z=1)
    k_proj2<<<dim3(HID / TN, (BNUM * SLEN) / TM, 2), 256, 4 * 2 * SLOT>>>(bv);

    // Ph[b,s,q] = f16(exp((1/32)*KM.q + vrow)) + col-sum partials
    k_sc<<<dim3(QLEN / TN, SLEN / TM, BNUM), 256, 4 * 2 * SLOT>>>(
        kmh, qh, ph, SLEN, QLEN, HID, 0.03125f,
        (size_t)SLEN * HID, (size_t)QLEN * HID, (size_t)SLEN * QLEN);

    // per-q inverse sums
    inv_k<<<(BNUM * QLEN) / 256, 256>>>();

    // merged: ctx GEMM (z<8, row-scaled by inv) + attn normalization (z>=8)
    k_ctxn<<<dim3(HID / TN, QLEN / TM, 16), 256, 4 * 2 * SLOT>>>(ctx, attn);
}